// round 9
// baseline (speedup 1.0000x reference)
#include <cuda_runtime.h>
#include <cuda_bf16.h>
#include <math.h>
#include <stdint.h>

#define BB 2
#define SS 1024
#define HIDN 4096
#define NH 32
#define NKV 8
#define HD 128
#define MTOK (BB*SS)
#define KVW (NKV*HD)
#define QSCALE 0.08838834764831845f

typedef __nv_bfloat16 bf16;

// ---------------- scratch ----------------
__device__ float g_rope[SS * 64 * 2];

__device__ bf16 g_hs_h[(size_t)MTOK * HIDN],  g_hs_l[(size_t)MTOK * HIDN];
__device__ bf16 g_wq_h[(size_t)HIDN * HIDN],  g_wq_l[(size_t)HIDN * HIDN];
__device__ bf16 g_wkv_h[(size_t)2 * KVW * HIDN], g_wkv_l[(size_t)2 * KVW * HIDN];
__device__ bf16 g_wo_h[(size_t)HIDN * HIDN],  g_wo_l[(size_t)HIDN * HIDN];

__device__ bf16 g_qh[(size_t)MTOK * HIDN], g_ql[(size_t)MTOK * HIDN];
__device__ bf16 g_kh[(size_t)MTOK * KVW],  g_kl[(size_t)MTOK * KVW];
__device__ bf16 g_vh[(size_t)MTOK * KVW],  g_vl[(size_t)MTOK * KVW];
__device__ bf16 g_ch[(size_t)MTOK * HIDN], g_cl[(size_t)MTOK * HIDN];

// ============================ helpers ====================================
__device__ __forceinline__ uint32_t smem_u32(const void* p) {
    uint32_t a;
    asm("{ .reg .u64 t; cvta.to.shared.u64 t, %1; cvt.u32.u64 %0, t; }" : "=r"(a) : "l"(p));
    return a;
}
__device__ __forceinline__ void cp16(uint32_t sdst, const void* gsrc) {
    asm volatile("cp.async.cg.shared.global [%0], [%1], 16;" :: "r"(sdst), "l"(gsrc));
}
__device__ __forceinline__ void cp_commit() {
    asm volatile("cp.async.commit_group;" ::: "memory");
}
template<int N> __device__ __forceinline__ void cp_wait() {
    asm volatile("cp.async.wait_group %0;" :: "n"(N) : "memory");
}
__device__ __forceinline__ void ldmx4(uint32_t* r, uint32_t addr) {
    asm volatile("ldmatrix.sync.aligned.m8n8.x4.shared.b16 {%0,%1,%2,%3}, [%4];"
                 : "=r"(r[0]), "=r"(r[1]), "=r"(r[2]), "=r"(r[3]) : "r"(addr));
}
__device__ __forceinline__ void ldmx2(uint32_t* r, uint32_t addr) {
    asm volatile("ldmatrix.sync.aligned.m8n8.x2.shared.b16 {%0,%1}, [%2];"
                 : "=r"(r[0]), "=r"(r[1]) : "r"(addr));
}
__device__ __forceinline__ void ldmx2t(uint32_t* r, uint32_t addr) {
    asm volatile("ldmatrix.sync.aligned.m8n8.x2.trans.shared.b16 {%0,%1}, [%2];"
                 : "=r"(r[0]), "=r"(r[1]) : "r"(addr));
}
__device__ __forceinline__ void mma_bf16(float* c, const uint32_t* a, const uint32_t* b) {
    asm volatile(
        "mma.sync.aligned.m16n8k16.row.col.f32.bf16.bf16.f32 "
        "{%0,%1,%2,%3}, {%4,%5,%6,%7}, {%8,%9}, {%0,%1,%2,%3};"
        : "+f"(c[0]), "+f"(c[1]), "+f"(c[2]), "+f"(c[3])
        : "r"(a[0]), "r"(a[1]), "r"(a[2]), "r"(a[3]), "r"(b[0]), "r"(b[1]));
}
__device__ __forceinline__ void mma_bf16b(float* c, const uint32_t* a, uint32_t b0, uint32_t b1) {
    asm volatile(
        "mma.sync.aligned.m16n8k16.row.col.f32.bf16.bf16.f32 "
        "{%0,%1,%2,%3}, {%4,%5,%6,%7}, {%8,%9}, {%0,%1,%2,%3};"
        : "+f"(c[0]), "+f"(c[1]), "+f"(c[2]), "+f"(c[3])
        : "r"(a[0]), "r"(a[1]), "r"(a[2]), "r"(a[3]), "r"(b0), "r"(b1));
}
__device__ __forceinline__ uint16_t bfbits(bf16 h) { return *(uint16_t*)&h; }

__device__ __forceinline__ void split_store(bf16* H, bf16* L, size_t idx, float a, float b) {
    bf16 h0 = __float2bfloat16(a);
    bf16 h1 = __float2bfloat16(b);
    bf16 l0 = __float2bfloat16(a - __bfloat162float(h0));
    bf16 l1 = __float2bfloat16(b - __bfloat162float(h1));
    uint32_t hp = ((uint32_t)bfbits(h1) << 16) | bfbits(h0);
    uint32_t lp = ((uint32_t)bfbits(l1) << 16) | bfbits(l0);
    *(uint32_t*)(H + idx) = hp;
    *(uint32_t*)(L + idx) = lp;
}

// ============================================================================
// Split-bf16 NT GEMM: 256 thr, 2x4 warps, 128x128 CTA tile, BK=32.
// 3-stage cp.async pipeline, ONE __syncthreads per chunk, packed 64B rows
// with XOR swizzle (conflict-free ldmatrix + stores). 2 CTAs/SM.
// EPI: 0 = fp32 store, 1 = Q (rope+scale+split), 2 = merged KV.
// ============================================================================
#define GBK 32
#define ARR_B (128 * 64)        // 8192 bytes per operand array
#define BUF_B (4 * ARR_B)       // 32768 bytes per stage
#define NSTAGE 3
#define GSM_BYTES (NSTAGE * BUF_B)  // 98304

// swizzled byte offset for (row, 16B-unit)
#define GSW(r, u) ((uint32_t)(r) * 64u + ((((uint32_t)(u) ^ (((uint32_t)(r) >> 1) & 3u)) << 4)))

template<int EPI>
__global__ __launch_bounds__(256, 2) void gemm_hmma(const bf16* __restrict__ Ah,
                                                    const bf16* __restrict__ Al,
                                                    const bf16* __restrict__ Bh,
                                                    const bf16* __restrict__ Bl,
                                                    float* __restrict__ Cf,
                                                    int M, int N, int K)
{
    extern __shared__ __align__(128) char sm[];
    const uint32_t smb = smem_u32(sm);
    const int tid = threadIdx.x;
    const int warp = tid >> 5, lane = tid & 31;
    const int wm = warp >> 2, wn = warp & 3;
    const int tn = blockIdx.x * 128;
    const int tm = blockIdx.y * 128;

    const char* gsrc[4];
    gsrc[0] = (const char*)(Ah + (size_t)tm * K);
    gsrc[1] = (const char*)(Al + (size_t)tm * K);
    gsrc[2] = (const char*)(Bh + (size_t)tn * K);
    gsrc[3] = (const char*)(Bl + (size_t)tn * K);
    const size_t rowb = (size_t)K * 2;

    float acc[4][4][4];
#pragma unroll
    for (int mt = 0; mt < 4; ++mt)
#pragma unroll
        for (int nt = 0; nt < 4; ++nt)
#pragma unroll
            for (int q = 0; q < 4; ++q) acc[mt][nt][q] = 0.f;

    const int nk = K / GBK;

    // issue loads for chunk c into stage s
    auto issue = [&](int c, int s) {
        const size_t coff = (size_t)c * 64;
        const uint32_t sb = smb + s * BUF_B;
#pragma unroll
        for (int a4 = 0; a4 < 4; ++a4) {
#pragma unroll
            for (int i = 0; i < 2; ++i) {
                int id = tid + i * 256;
                int r = id >> 2;
                int c8 = id & 3;
                cp16(sb + a4 * ARR_B + GSW(r, c8),
                     gsrc[a4] + (size_t)r * rowb + coff + c8 * 16);
            }
        }
    };

    issue(0, 0); cp_commit();
    issue(1, 1); cp_commit();

    for (int kc = 0; kc < nk; ++kc) {
        cp_wait<1>();          // chunk kc's group complete
        __syncthreads();       // visibility + all warps done with stage (kc+2)%3
        if (kc + 2 < nk) issue(kc + 2, (kc + 2) % NSTAGE);
        cp_commit();           // one group per iteration (possibly empty)

        const uint32_t st = smb + (kc % NSTAGE) * BUF_B;
        const uint32_t sAh = st + 0 * ARR_B;
        const uint32_t sAl = st + 1 * ARR_B;
        const uint32_t sBh = st + 2 * ARR_B;
        const uint32_t sBl = st + 3 * ARR_B;

#pragma unroll
        for (int ks = 0; ks < 2; ++ks) {
            uint32_t a[4][4], b[2][4], b2[2][4];
            const uint32_t cu = (uint32_t)(ks * 2 + (lane >> 4));   // 16B unit 0..3
#pragma unroll
            for (int mt = 0; mt < 4; ++mt) {
                uint32_t r = (uint32_t)(wm * 64 + mt * 16 + (lane & 15));
                ldmx4(a[mt], sAh + GSW(r, cu));
            }
#pragma unroll
            for (int np = 0; np < 2; ++np) {
                uint32_t r = (uint32_t)(wn * 32 + np * 16 + (lane & 15));
                ldmx4(b[np], sBh + GSW(r, cu));
                ldmx4(b2[np], sBl + GSW(r, cu));
            }
            // ah * bh
#pragma unroll
            for (int mt = 0; mt < 4; ++mt)
#pragma unroll
                for (int np = 0; np < 2; ++np) {
                    mma_bf16b(acc[mt][2*np],   a[mt], b[np][0], b[np][2]);
                    mma_bf16b(acc[mt][2*np+1], a[mt], b[np][1], b[np][3]);
                }
            // ah * bl
#pragma unroll
            for (int mt = 0; mt < 4; ++mt)
#pragma unroll
                for (int np = 0; np < 2; ++np) {
                    mma_bf16b(acc[mt][2*np],   a[mt], b2[np][0], b2[np][2]);
                    mma_bf16b(acc[mt][2*np+1], a[mt], b2[np][1], b2[np][3]);
                }
            // al * bh (al overwrites a)
#pragma unroll
            for (int mt = 0; mt < 4; ++mt) {
                uint32_t r = (uint32_t)(wm * 64 + mt * 16 + (lane & 15));
                ldmx4(a[mt], sAl + GSW(r, cu));
            }
#pragma unroll
            for (int mt = 0; mt < 4; ++mt)
#pragma unroll
                for (int np = 0; np < 2; ++np) {
                    mma_bf16b(acc[mt][2*np],   a[mt], b[np][0], b[np][2]);
                    mma_bf16b(acc[mt][2*np+1], a[mt], b[np][1], b[np][3]);
                }
        }
    }

    // ---- epilogue ----
#pragma unroll
    for (int mt = 0; mt < 4; ++mt) {
        int row0 = tm + wm * 64 + mt * 16 + (lane >> 2);
#pragma unroll
        for (int nt = 0; nt < 4; ++nt) {
            int col = tn + wn * 32 + (nt >> 1) * 16 + (nt & 1) * 8 + (lane & 3) * 2;
            float c0 = acc[mt][nt][0], c1 = acc[mt][nt][1];
            float c2 = acc[mt][nt][2], c3 = acc[mt][nt][3];
            if (EPI == 0) {
                *(float2*)(Cf + (size_t)row0 * N + col) = make_float2(c0, c1);
                *(float2*)(Cf + (size_t)(row0 + 8) * N + col) = make_float2(c2, c3);
            } else {
                const int i = (col & 127) >> 1;
#pragma unroll
                for (int rr = 0; rr < 2; ++rr) {
                    int row = row0 + rr * 8;
                    float e = rr ? c2 : c0;
                    float o = rr ? c3 : c1;
                    int s = row & (SS - 1);
                    if (EPI == 1) {
                        float2 cs = *(const float2*)&g_rope[(s * 64 + i) * 2];
                        float oe = (e * cs.x - o * cs.y) * QSCALE;
                        float oo = (e * cs.y + o * cs.x) * QSCALE;
                        split_store(g_qh, g_ql, (size_t)row * HIDN + col, oe, oo);
                    } else {
                        if (col < KVW) {
                            float2 cs = *(const float2*)&g_rope[(s * 64 + i) * 2];
                            float oe = e * cs.x - o * cs.y;
                            float oo = e * cs.y + o * cs.x;
                            split_store(g_kh, g_kl, (size_t)row * KVW + col, oe, oo);
                        } else {
                            split_store(g_vh, g_vl, (size_t)row * KVW + (col - KVW), e, o);
                        }
                    }
                }
            }
        }
    }
}

// ============================================================================
// One-shot conversion of hs + all weights into bf16 hi/lo (segmented).
// ============================================================================
__global__ void cvt_all(const float* __restrict__ hs, const float* __restrict__ Wq,
                        const float* __restrict__ Wk, const float* __restrict__ Wv,
                        const float* __restrict__ Wo)
{
    const size_t n_hs = (size_t)MTOK * HIDN / 4;
    const size_t n_wq = (size_t)HIDN * HIDN / 4;
    const size_t n_wk = (size_t)KVW * HIDN / 4;
    const size_t total = n_hs + n_wq + 2 * n_wk + n_wq;
    size_t i = (size_t)blockIdx.x * blockDim.x + threadIdx.x;
    if (i >= total) return;

    const float* src;
    bf16 *H, *L;
    size_t k;
    if (i < n_hs) {
        src = hs; H = g_hs_h; L = g_hs_l; k = i;
    } else if (i < n_hs + n_wq) {
        src = Wq; H = g_wq_h; L = g_wq_l; k = i - n_hs;
    } else if (i < n_hs + n_wq + n_wk) {
        src = Wk; H = g_wkv_h; L = g_wkv_l; k = i - n_hs - n_wq;
    } else if (i < n_hs + n_wq + 2 * n_wk) {
        src = Wv; k = i - n_hs - n_wq - n_wk;
        H = g_wkv_h + (size_t)KVW * HIDN; L = g_wkv_l + (size_t)KVW * HIDN;
    } else {
        src = Wo; H = g_wo_h; L = g_wo_l; k = i - n_hs - n_wq - 2 * n_wk;
    }

    float4 v = ((const float4*)src)[k];
    bf16 h[4], l[4];
    float x[4] = {v.x, v.y, v.z, v.w};
#pragma unroll
    for (int j = 0; j < 4; ++j) {
        h[j] = __float2bfloat16(x[j]);
        l[j] = __float2bfloat16(x[j] - __bfloat162float(h[j]));
    }
    *(uint2*)(H + k * 4) = *(uint2*)h;
    *(uint2*)(L + k * 4) = *(uint2*)l;
}

// ============================================================================
// RoPE table
// ============================================================================
__global__ void rope_table()
{
    int idx = blockIdx.x * blockDim.x + threadIdx.x;
    if (idx >= SS * 64) return;
    int s = idx >> 6, i = idx & 63;
    double inv = exp(-(double)i * (log(10000.0) / 64.0));
    double sn, cs;
    sincos((double)s * inv, &sn, &cs);
    g_rope[idx * 2 + 0] = (float)cs;
    g_rope[idx * 2 + 1] = (float)sn;
}

// ============================================================================
// HMMA flash attention (split bf16, 3-pass). Epilogue writes split C.
// ============================================================================
#define ASW(row, colu) ((uint32_t)(row) * 256 + ((((uint32_t)(colu)) ^ ((row) & 7)) << 4))
#define AT_Q_H 0
#define AT_Q_L 16384
#define AT_K_H 32768
#define AT_K_L 49152
#define AT_V_H 65536
#define AT_V_L 81920
#define AT_SMEM 98304

__global__ __launch_bounds__(128) void attn_hmma(const bf16* __restrict__ Qh,
                                                 const bf16* __restrict__ Ql,
                                                 const bf16* __restrict__ Kh,
                                                 const bf16* __restrict__ Kl,
                                                 const bf16* __restrict__ Vh,
                                                 const bf16* __restrict__ Vl,
                                                 bf16* __restrict__ Ch,
                                                 bf16* __restrict__ Cl)
{
    extern __shared__ __align__(128) char sm[];
    const uint32_t smb = smem_u32(sm);
    const int mb = blockIdx.x;
    const int h = blockIdx.y;
    const int b = blockIdx.z;
    const int kvh = h >> 2;
    const int tid = threadIdx.x;
    const int warp = tid >> 5, lane = tid & 31;

    {
        const char* gqh = (const char*)(Qh + ((size_t)(b * SS + mb * 64)) * HIDN + h * HD);
        const char* gql = (const char*)(Ql + ((size_t)(b * SS + mb * 64)) * HIDN + h * HD);
#pragma unroll
        for (int t = 0; t < 8; ++t) {
            int id = tid + t * 128;
            int r = id >> 4;
            int cu = id & 15;
            cp16(smb + AT_Q_H + ASW(r, cu), gqh + (size_t)r * (HIDN * 2) + cu * 16);
            cp16(smb + AT_Q_L + ASW(r, cu), gql + (size_t)r * (HIDN * 2) + cu * 16);
        }
        cp_commit();
    }

    float o[16][4];
#pragma unroll
    for (int nt = 0; nt < 16; ++nt)
#pragma unroll
        for (int q = 0; q < 4; ++q) o[nt][q] = 0.f;
    float m_a = -INFINITY, m_b = -INFINITY, l_a = 0.f, l_b = 0.f;

    const int rowA = warp * 16 + (lane >> 2);
    const int grow_a = mb * 64 + rowA;
    const int grow_b = grow_a + 8;

    for (int nb = 0; nb <= mb; ++nb) {
        {
            const char* gkh = (const char*)(Kh + ((size_t)(b * SS + nb * 64)) * KVW + kvh * HD);
            const char* gkl = (const char*)(Kl + ((size_t)(b * SS + nb * 64)) * KVW + kvh * HD);
            const char* gvh = (const char*)(Vh + ((size_t)(b * SS + nb * 64)) * KVW + kvh * HD);
            const char* gvl = (const char*)(Vl + ((size_t)(b * SS + nb * 64)) * KVW + kvh * HD);
#pragma unroll
            for (int t = 0; t < 8; ++t) {
                int id = tid + t * 128;
                int r = id >> 4;
                int cu = id & 15;
                size_t go = (size_t)r * (KVW * 2) + cu * 16;
                uint32_t so = ASW(r, cu);
                cp16(smb + AT_K_H + so, gkh + go);
                cp16(smb + AT_K_L + so, gkl + go);
                cp16(smb + AT_V_H + so, gvh + go);
                cp16(smb + AT_V_L + so, gvl + go);
            }
            cp_commit();
            cp_wait<0>();
        }
        __syncthreads();

        float s[8][4];
#pragma unroll
        for (int j = 0; j < 8; ++j)
#pragma unroll
            for (int q = 0; q < 4; ++q) s[j][q] = 0.f;

#pragma unroll
        for (int ks = 0; ks < 8; ++ks) {
            uint32_t ah[4], al[4];
            {
                int r = warp * 16 + (lane & 15);
                int cu = ks * 2 + (lane >> 4);
                ldmx4(ah, smb + AT_Q_H + ASW(r, cu));
                ldmx4(al, smb + AT_Q_L + ASW(r, cu));
            }
#pragma unroll
            for (int j = 0; j < 8; ++j) {
                uint32_t bh[2], bl[2];
                int r = j * 8 + (lane & 7);
                int cu = ks * 2 + ((lane >> 3) & 1);
                ldmx2(bh, smb + AT_K_H + ASW(r, cu));
                ldmx2(bl, smb + AT_K_L + ASW(r, cu));
                mma_bf16(s[j], ah, bh);
                mma_bf16(s[j], ah, bl);
                mma_bf16(s[j], al, bh);
            }
        }

        if (nb == mb) {
#pragma unroll
            for (int j = 0; j < 8; ++j) {
                int col = nb * 64 + j * 8 + (lane & 3) * 2;
                if (col > grow_a)     s[j][0] = -1e30f;
                if (col + 1 > grow_a) s[j][1] = -1e30f;
                if (col > grow_b)     s[j][2] = -1e30f;
                if (col + 1 > grow_b) s[j][3] = -1e30f;
            }
        }

        float mx_a = -INFINITY, mx_b = -INFINITY;
#pragma unroll
        for (int j = 0; j < 8; ++j) {
            mx_a = fmaxf(mx_a, fmaxf(s[j][0], s[j][1]));
            mx_b = fmaxf(mx_b, fmaxf(s[j][2], s[j][3]));
        }
        mx_a = fmaxf(mx_a, __shfl_xor_sync(0xffffffffu, mx_a, 1));
        mx_a = fmaxf(mx_a, __shfl_xor_sync(0xffffffffu, mx_a, 2));
        mx_b = fmaxf(mx_b, __shfl_xor_sync(0xffffffffu, mx_b, 1));
        mx_b = fmaxf(mx_b, __shfl_xor_sync(0xffffffffu, mx_b, 2));

        float nm_a = fmaxf(m_a, mx_a);
        float nm_b = fmaxf(m_b, mx_b);
        float corr_a = __expf(m_a - nm_a);
        float corr_b = __expf(m_b - nm_b);
        m_a = nm_a; m_b = nm_b;

        float sum_a = 0.f, sum_b = 0.f;
#pragma unroll
        for (int j = 0; j < 8; ++j) {
            s[j][0] = __expf(s[j][0] - nm_a);
            s[j][1] = __expf(s[j][1] - nm_a);
            s[j][2] = __expf(s[j][2] - nm_b);
            s[j][3] = __expf(s[j][3] - nm_b);
            sum_a += s[j][0] + s[j][1];
            sum_b += s[j][2] + s[j][3];
        }
        sum_a += __shfl_xor_sync(0xffffffffu, sum_a, 1);
        sum_a += __shfl_xor_sync(0xffffffffu, sum_a, 2);
        sum_b += __shfl_xor_sync(0xffffffffu, sum_b, 1);
        sum_b += __shfl_xor_sync(0xffffffffu, sum_b, 2);
        l_a = l_a * corr_a + sum_a;
        l_b = l_b * corr_b + sum_b;

#pragma unroll
        for (int nt = 0; nt < 16; ++nt) {
            o[nt][0] *= corr_a; o[nt][1] *= corr_a;
            o[nt][2] *= corr_b; o[nt][3] *= corr_b;
        }

        uint32_t ph[4][4], pl[4][4];
#pragma unroll
        for (int ks = 0; ks < 4; ++ks) {
            const float* t0 = s[2 * ks];
            const float* t1 = s[2 * ks + 1];
            float v0[8] = {t0[0], t0[1], t0[2], t0[3], t1[0], t1[1], t1[2], t1[3]};
            uint16_t hb[8]; float rs[8];
#pragma unroll
            for (int e = 0; e < 8; ++e) {
                bf16 hh = __float2bfloat16(v0[e]);
                hb[e] = bfbits(hh);
                rs[e] = v0[e] - __bfloat162float(hh);
            }
            ph[ks][0] = ((uint32_t)hb[1] << 16) | hb[0];
            ph[ks][1] = ((uint32_t)hb[3] << 16) | hb[2];
            ph[ks][2] = ((uint32_t)hb[5] << 16) | hb[4];
            ph[ks][3] = ((uint32_t)hb[7] << 16) | hb[6];
            uint16_t lb[8];
#pragma unroll
            for (int e = 0; e < 8; ++e) lb[e] = bfbits(__float2bfloat16(rs[e]));
            pl[ks][0] = ((uint32_t)lb[1] << 16) | lb[0];
            pl[ks][1] = ((uint32_t)lb[3] << 16) | lb[2];
            pl[ks][2] = ((uint32_t)lb[5] << 16) | lb[4];
            pl[ks][3] = ((uint32_t)lb[7] << 16) | lb[6];
        }

#pragma unroll
        for (int nt = 0; nt < 16; ++nt) {
#pragma unroll
            for (int ks = 0; ks < 4; ++ks) {
                uint32_t bh[2], bl[2];
                int r = ks * 16 + (lane & 15);
                ldmx2t(bh, smb + AT_V_H + ASW(r, nt));
                ldmx2t(bl, smb + AT_V_L + ASW(r, nt));
                mma_bf16(o[nt], ph[ks], bh);
                mma_bf16(o[nt], ph[ks], bl);
                mma_bf16(o[nt], pl[ks], bh);
            }
        }
        __syncthreads();
    }

    const float inv_a = 1.f / l_a;
    const float inv_b = 1.f / l_b;
    const size_t ra = ((size_t)(b * SS + mb * 64 + rowA)) * HIDN + h * HD;
    const size_t rb = ra + (size_t)8 * HIDN;
#pragma unroll
    for (int nt = 0; nt < 16; ++nt) {
        int col = nt * 8 + (lane & 3) * 2;
        split_store(Ch, Cl, ra + col, o[nt][0] * inv_a, o[nt][1] * inv_a);
        split_store(Ch, Cl, rb + col, o[nt][2] * inv_b, o[nt][3] * inv_b);
    }
}

// ============================================================================
// Launch
// ============================================================================
extern "C" void kernel_launch(void* const* d_in, const int* in_sizes, int n_in,
                              void* d_out, int out_size)
{
    (void)in_sizes; (void)n_in; (void)out_size;
    const float* hs = (const float*)d_in[0];
    const float* Wq = (const float*)d_in[1];
    const float* Wk = (const float*)d_in[2];
    const float* Wv = (const float*)d_in[3];
    const float* Wo = (const float*)d_in[4];
    float* out = (float*)d_out;

    bf16 *hsh, *hsl, *wqh, *wql, *wkvh, *wkvl, *woh, *wol;
    bf16 *qh, *ql, *kh, *kl, *vh, *vl, *ch, *cl;
    cudaGetSymbolAddress((void**)&hsh, g_hs_h);   cudaGetSymbolAddress((void**)&hsl, g_hs_l);
    cudaGetSymbolAddress((void**)&wqh, g_wq_h);   cudaGetSymbolAddress((void**)&wql, g_wq_l);
    cudaGetSymbolAddress((void**)&wkvh, g_wkv_h); cudaGetSymbolAddress((void**)&wkvl, g_wkv_l);
    cudaGetSymbolAddress((void**)&woh, g_wo_h);   cudaGetSymbolAddress((void**)&wol, g_wo_l);
    cudaGetSymbolAddress((void**)&qh, g_qh);      cudaGetSymbolAddress((void**)&ql, g_ql);
    cudaGetSymbolAddress((void**)&kh, g_kh);      cudaGetSymbolAddress((void**)&kl, g_kl);
    cudaGetSymbolAddress((void**)&vh, g_vh);      cudaGetSymbolAddress((void**)&vl, g_vl);
    cudaGetSymbolAddress((void**)&ch, g_ch);      cudaGetSymbolAddress((void**)&cl, g_cl);

    cudaFuncSetAttribute(gemm_hmma<0>, cudaFuncAttributeMaxDynamicSharedMemorySize, GSM_BYTES);
    cudaFuncSetAttribute(gemm_hmma<1>, cudaFuncAttributeMaxDynamicSharedMemorySize, GSM_BYTES);
    cudaFuncSetAttribute(gemm_hmma<2>, cudaFuncAttributeMaxDynamicSharedMemorySize, GSM_BYTES);
    cudaFuncSetAttribute(attn_hmma, cudaFuncAttributeMaxDynamicSharedMemorySize, AT_SMEM);

    // 0: rope table
    rope_table<<<(SS * 64 + 255) / 256, 256>>>();
    // 1: all conversions in one kernel
    {
        size_t total = (size_t)MTOK * HIDN / 4 + 2 * (size_t)HIDN * HIDN / 4 + 2 * (size_t)KVW * HIDN / 4;
        cvt_all<<<(unsigned)((total + 255) / 256), 256>>>(hs, Wq, Wk, Wv, Wo);
    }
    // 2: Q projection (rope+scale+split fused)
    gemm_hmma<1><<<dim3(HIDN / 128, MTOK / 128), 256, GSM_BYTES>>>(hsh, hsl, wqh, wql, nullptr, MTOK, HIDN, HIDN);
    // 3: merged K|V projection
    gemm_hmma<2><<<dim3(2 * KVW / 128, MTOK / 128), 256, GSM_BYTES>>>(hsh, hsl, wkvh, wkvl, nullptr, MTOK, 2 * KVW, HIDN);
    // 4: attention
    attn_hmma<<<dim3(SS / 64, NH, BB), 128, AT_SMEM>>>(qh, ql, kh, kl, vh, vl, ch, cl);
    // 5: output projection
    gemm_hmma<0><<<dim3(HIDN / 128, MTOK / 128), 256, GSM_BYTES>>>(ch, cl, woh, wol, out, MTOK, HIDN, HIDN);
}

// round 10
// speedup vs baseline: 1.0071x; 1.0071x over previous
#include <cuda_runtime.h>
#include <cuda_bf16.h>
#include <math.h>
#include <stdint.h>

#define BB 2
#define SS 1024
#define HIDN 4096
#define NH 32
#define NKV 8
#define HD 128
#define MTOK (BB*SS)
#define KVW (NKV*HD)
#define QSCALE 0.08838834764831845f

typedef __nv_bfloat16 bf16;

// ---------------- scratch ----------------
__device__ float g_rope[SS * 64 * 2];

__device__ bf16 g_hs_h[(size_t)MTOK * HIDN],  g_hs_l[(size_t)MTOK * HIDN];
__device__ bf16 g_wq_h[(size_t)HIDN * HIDN],  g_wq_l[(size_t)HIDN * HIDN];
__device__ bf16 g_wkv_h[(size_t)2 * KVW * HIDN], g_wkv_l[(size_t)2 * KVW * HIDN];
__device__ bf16 g_wo_h[(size_t)HIDN * HIDN],  g_wo_l[(size_t)HIDN * HIDN];

__device__ bf16 g_qh[(size_t)MTOK * HIDN], g_ql[(size_t)MTOK * HIDN];
__device__ bf16 g_kh[(size_t)MTOK * KVW],  g_kl[(size_t)MTOK * KVW];
__device__ bf16 g_vh[(size_t)MTOK * KVW],  g_vl[(size_t)MTOK * KVW];
__device__ bf16 g_ch[(size_t)MTOK * HIDN], g_cl[(size_t)MTOK * HIDN];

// ============================ helpers ====================================
__device__ __forceinline__ uint32_t smem_u32(const void* p) {
    uint32_t a;
    asm("{ .reg .u64 t; cvta.to.shared.u64 t, %1; cvt.u32.u64 %0, t; }" : "=r"(a) : "l"(p));
    return a;
}
__device__ __forceinline__ void cp16(uint32_t sdst, const void* gsrc) {
    asm volatile("cp.async.cg.shared.global [%0], [%1], 16;" :: "r"(sdst), "l"(gsrc));
}
__device__ __forceinline__ void cp_commit() {
    asm volatile("cp.async.commit_group;" ::: "memory");
}
template<int N> __device__ __forceinline__ void cp_wait() {
    asm volatile("cp.async.wait_group %0;" :: "n"(N) : "memory");
}
__device__ __forceinline__ void ldmx4(uint32_t* r, uint32_t addr) {
    asm volatile("ldmatrix.sync.aligned.m8n8.x4.shared.b16 {%0,%1,%2,%3}, [%4];"
                 : "=r"(r[0]), "=r"(r[1]), "=r"(r[2]), "=r"(r[3]) : "r"(addr));
}
__device__ __forceinline__ void ldmx2(uint32_t* r, uint32_t addr) {
    asm volatile("ldmatrix.sync.aligned.m8n8.x2.shared.b16 {%0,%1}, [%2];"
                 : "=r"(r[0]), "=r"(r[1]) : "r"(addr));
}
__device__ __forceinline__ void ldmx2t(uint32_t* r, uint32_t addr) {
    asm volatile("ldmatrix.sync.aligned.m8n8.x2.trans.shared.b16 {%0,%1}, [%2];"
                 : "=r"(r[0]), "=r"(r[1]) : "r"(addr));
}
__device__ __forceinline__ void mma_bf16(float* c, const uint32_t* a, const uint32_t* b) {
    asm volatile(
        "mma.sync.aligned.m16n8k16.row.col.f32.bf16.bf16.f32 "
        "{%0,%1,%2,%3}, {%4,%5,%6,%7}, {%8,%9}, {%0,%1,%2,%3};"
        : "+f"(c[0]), "+f"(c[1]), "+f"(c[2]), "+f"(c[3])
        : "r"(a[0]), "r"(a[1]), "r"(a[2]), "r"(a[3]), "r"(b[0]), "r"(b[1]));
}
__device__ __forceinline__ void mma_bf16b(float* c, const uint32_t* a, uint32_t b0, uint32_t b1) {
    asm volatile(
        "mma.sync.aligned.m16n8k16.row.col.f32.bf16.bf16.f32 "
        "{%0,%1,%2,%3}, {%4,%5,%6,%7}, {%8,%9}, {%0,%1,%2,%3};"
        : "+f"(c[0]), "+f"(c[1]), "+f"(c[2]), "+f"(c[3])
        : "r"(a[0]), "r"(a[1]), "r"(a[2]), "r"(a[3]), "r"(b0), "r"(b1));
}
__device__ __forceinline__ uint16_t bfbits(bf16 h) { return *(uint16_t*)&h; }

__device__ __forceinline__ void split_store(bf16* H, bf16* L, size_t idx, float a, float b) {
    bf16 h0 = __float2bfloat16(a);
    bf16 h1 = __float2bfloat16(b);
    bf16 l0 = __float2bfloat16(a - __bfloat162float(h0));
    bf16 l1 = __float2bfloat16(b - __bfloat162float(h1));
    uint32_t hp = ((uint32_t)bfbits(h1) << 16) | bfbits(h0);
    uint32_t lp = ((uint32_t)bfbits(l1) << 16) | bfbits(l0);
    *(uint32_t*)(H + idx) = hp;
    *(uint32_t*)(L + idx) = lp;
}

// ============================================================================
// Split-bf16 NT GEMM: 256 thr, 2x4 warps, 128x128 CTA tile, BK=32.
// 3-stage cp.async pipeline, ONE __syncthreads per chunk, packed 64B rows with
// XOR swizzle. Swizzled ldmatrix offsets PRECOMPUTED (no per-iter ALU), and
// the al-reload is interleaved with remaining MMAs. 2 CTAs/SM.
// EPI: 0 = fp32 store, 1 = Q (rope+scale+split), 2 = merged KV.
// ============================================================================
#define GBK 32
#define ARR_B (128 * 64)
#define BUF_B (4 * ARR_B)
#define NSTAGE 3
#define GSM_BYTES (NSTAGE * BUF_B)  // 98304

#define GSW(r, u) ((uint32_t)(r) * 64u + ((((uint32_t)(u) ^ (((uint32_t)(r) >> 1) & 3u)) << 4)))

template<int EPI>
__global__ __launch_bounds__(256, 2) void gemm_hmma(const bf16* __restrict__ Ah,
                                                    const bf16* __restrict__ Al,
                                                    const bf16* __restrict__ Bh,
                                                    const bf16* __restrict__ Bl,
                                                    float* __restrict__ Cf,
                                                    int M, int N, int K)
{
    extern __shared__ __align__(128) char sm[];
    const uint32_t smb = smem_u32(sm);
    const int tid = threadIdx.x;
    const int warp = tid >> 5, lane = tid & 31;
    const int wm = warp >> 2, wn = warp & 3;
    const int tn = blockIdx.x * 128;
    const int tm = blockIdx.y * 128;

    const char* gsrc[4];
    gsrc[0] = (const char*)(Ah + (size_t)tm * K);
    gsrc[1] = (const char*)(Al + (size_t)tm * K);
    gsrc[2] = (const char*)(Bh + (size_t)tn * K);
    gsrc[3] = (const char*)(Bl + (size_t)tn * K);
    const size_t rowb = (size_t)K * 2;

    float acc[4][4][4];
#pragma unroll
    for (int mt = 0; mt < 4; ++mt)
#pragma unroll
        for (int nt = 0; nt < 4; ++nt)
#pragma unroll
            for (int q = 0; q < 4; ++q) acc[mt][nt][q] = 0.f;

    // ---- precomputed swizzled ldmatrix offsets (within an operand array) ----
    uint32_t offA[2][4], offB[2][2];
#pragma unroll
    for (int ks = 0; ks < 2; ++ks) {
        uint32_t cu = (uint32_t)(ks * 2 + (lane >> 4));
#pragma unroll
        for (int mt = 0; mt < 4; ++mt)
            offA[ks][mt] = GSW((uint32_t)(wm * 64 + mt * 16 + (lane & 15)), cu);
#pragma unroll
        for (int np = 0; np < 2; ++np)
            offB[ks][np] = GSW((uint32_t)(wn * 32 + np * 16 + (lane & 15)), cu);
    }
    // precomputed store offsets for cp.async
    uint32_t offS[2];
    {
        int r = tid >> 2;
#pragma unroll
        for (int i = 0; i < 2; ++i) {
            int id = tid + i * 256;
            offS[i] = GSW((uint32_t)(id >> 2), (uint32_t)(id & 3));
        }
        (void)r;
    }

    const int nk = K / GBK;

    auto issue = [&](int c, int s) {
        const size_t coff = (size_t)c * 64;
        const uint32_t sb = smb + s * BUF_B;
#pragma unroll
        for (int a4 = 0; a4 < 4; ++a4) {
#pragma unroll
            for (int i = 0; i < 2; ++i) {
                int id = tid + i * 256;
                cp16(sb + a4 * ARR_B + offS[i],
                     gsrc[a4] + (size_t)(id >> 2) * rowb + coff + (id & 3) * 16);
            }
        }
    };

    issue(0, 0); cp_commit();
    issue(1, 1); cp_commit();

    for (int kc = 0; kc < nk; ++kc) {
        cp_wait<1>();
        __syncthreads();
        if (kc + 2 < nk) issue(kc + 2, (kc + 2) % NSTAGE);
        cp_commit();

        const uint32_t st = smb + (kc % NSTAGE) * BUF_B;
        const uint32_t sAh = st + 0 * ARR_B;
        const uint32_t sAl = st + 1 * ARR_B;
        const uint32_t sBh = st + 2 * ARR_B;
        const uint32_t sBl = st + 3 * ARR_B;

#pragma unroll
        for (int ks = 0; ks < 2; ++ks) {
            uint32_t a[4][4], b[2][4], b2[2][4];
#pragma unroll
            for (int np = 0; np < 2; ++np) {
                ldmx4(b[np], sBh + offB[ks][np]);
                ldmx4(b2[np], sBl + offB[ks][np]);
            }
#pragma unroll
            for (int mt = 0; mt < 4; ++mt)
                ldmx4(a[mt], sAh + offA[ks][mt]);

            // per-mt: ah*bh, ah*bl, then immediately reload a[mt] <- al
#pragma unroll
            for (int mt = 0; mt < 4; ++mt) {
#pragma unroll
                for (int np = 0; np < 2; ++np) {
                    mma_bf16b(acc[mt][2*np],   a[mt], b[np][0], b[np][2]);
                    mma_bf16b(acc[mt][2*np+1], a[mt], b[np][1], b[np][3]);
                }
#pragma unroll
                for (int np = 0; np < 2; ++np) {
                    mma_bf16b(acc[mt][2*np],   a[mt], b2[np][0], b2[np][2]);
                    mma_bf16b(acc[mt][2*np+1], a[mt], b2[np][1], b2[np][3]);
                }
                ldmx4(a[mt], sAl + offA[ks][mt]);
            }
            // al * bh
#pragma unroll
            for (int mt = 0; mt < 4; ++mt)
#pragma unroll
                for (int np = 0; np < 2; ++np) {
                    mma_bf16b(acc[mt][2*np],   a[mt], b[np][0], b[np][2]);
                    mma_bf16b(acc[mt][2*np+1], a[mt], b[np][1], b[np][3]);
                }
        }
    }

    // ---- epilogue ----
#pragma unroll
    for (int mt = 0; mt < 4; ++mt) {
        int row0 = tm + wm * 64 + mt * 16 + (lane >> 2);
#pragma unroll
        for (int nt = 0; nt < 4; ++nt) {
            int col = tn + wn * 32 + (nt >> 1) * 16 + (nt & 1) * 8 + (lane & 3) * 2;
            float c0 = acc[mt][nt][0], c1 = acc[mt][nt][1];
            float c2 = acc[mt][nt][2], c3 = acc[mt][nt][3];
            if (EPI == 0) {
                *(float2*)(Cf + (size_t)row0 * N + col) = make_float2(c0, c1);
                *(float2*)(Cf + (size_t)(row0 + 8) * N + col) = make_float2(c2, c3);
            } else {
                const int i = (col & 127) >> 1;
#pragma unroll
                for (int rr = 0; rr < 2; ++rr) {
                    int row = row0 + rr * 8;
                    float e = rr ? c2 : c0;
                    float o = rr ? c3 : c1;
                    int s = row & (SS - 1);
                    if (EPI == 1) {
                        float2 cs = *(const float2*)&g_rope[(s * 64 + i) * 2];
                        float oe = (e * cs.x - o * cs.y) * QSCALE;
                        float oo = (e * cs.y + o * cs.x) * QSCALE;
                        split_store(g_qh, g_ql, (size_t)row * HIDN + col, oe, oo);
                    } else {
                        if (col < KVW) {
                            float2 cs = *(const float2*)&g_rope[(s * 64 + i) * 2];
                            float oe = e * cs.x - o * cs.y;
                            float oo = e * cs.y + o * cs.x;
                            split_store(g_kh, g_kl, (size_t)row * KVW + col, oe, oo);
                        } else {
                            split_store(g_vh, g_vl, (size_t)row * KVW + (col - KVW), e, o);
                        }
                    }
                }
            }
        }
    }
}

// ============================================================================
// One-shot conversion of hs + all weights into bf16 hi/lo (segmented).
// ============================================================================
__global__ void cvt_all(const float* __restrict__ hs, const float* __restrict__ Wq,
                        const float* __restrict__ Wk, const float* __restrict__ Wv,
                        const float* __restrict__ Wo)
{
    const size_t n_hs = (size_t)MTOK * HIDN / 4;
    const size_t n_wq = (size_t)HIDN * HIDN / 4;
    const size_t n_wk = (size_t)KVW * HIDN / 4;
    const size_t total = n_hs + n_wq + 2 * n_wk + n_wq;
    size_t i = (size_t)blockIdx.x * blockDim.x + threadIdx.x;
    if (i >= total) return;

    const float* src;
    bf16 *H, *L;
    size_t k;
    if (i < n_hs) {
        src = hs; H = g_hs_h; L = g_hs_l; k = i;
    } else if (i < n_hs + n_wq) {
        src = Wq; H = g_wq_h; L = g_wq_l; k = i - n_hs;
    } else if (i < n_hs + n_wq + n_wk) {
        src = Wk; H = g_wkv_h; L = g_wkv_l; k = i - n_hs - n_wq;
    } else if (i < n_hs + n_wq + 2 * n_wk) {
        src = Wv; k = i - n_hs - n_wq - n_wk;
        H = g_wkv_h + (size_t)KVW * HIDN; L = g_wkv_l + (size_t)KVW * HIDN;
    } else {
        src = Wo; H = g_wo_h; L = g_wo_l; k = i - n_hs - n_wq - 2 * n_wk;
    }

    float4 v = ((const float4*)src)[k];
    bf16 h[4], l[4];
    float x[4] = {v.x, v.y, v.z, v.w};
#pragma unroll
    for (int j = 0; j < 4; ++j) {
        h[j] = __float2bfloat16(x[j]);
        l[j] = __float2bfloat16(x[j] - __bfloat162float(h[j]));
    }
    *(uint2*)(H + k * 4) = *(uint2*)h;
    *(uint2*)(L + k * 4) = *(uint2*)l;
}

// ============================================================================
// RoPE table
// ============================================================================
__global__ void rope_table()
{
    int idx = blockIdx.x * blockDim.x + threadIdx.x;
    if (idx >= SS * 64) return;
    int s = idx >> 6, i = idx & 63;
    double inv = exp(-(double)i * (log(10000.0) / 64.0));
    double sn, cs;
    sincos((double)s * inv, &sn, &cs);
    g_rope[idx * 2 + 0] = (float)cs;
    g_rope[idx * 2 + 1] = (float)sn;
}

// ============================================================================
// HMMA flash attention (split bf16, 3-pass). Epilogue writes split C.
// ============================================================================
#define ASW(row, colu) ((uint32_t)(row) * 256 + ((((uint32_t)(colu)) ^ ((row) & 7)) << 4))
#define AT_Q_H 0
#define AT_Q_L 16384
#define AT_K_H 32768
#define AT_K_L 49152
#define AT_V_H 65536
#define AT_V_L 81920
#define AT_SMEM 98304

__global__ __launch_bounds__(128) void attn_hmma(const bf16* __restrict__ Qh,
                                                 const bf16* __restrict__ Ql,
                                                 const bf16* __restrict__ Kh,
                                                 const bf16* __restrict__ Kl,
                                                 const bf16* __restrict__ Vh,
                                                 const bf16* __restrict__ Vl,
                                                 bf16* __restrict__ Ch,
                                                 bf16* __restrict__ Cl)
{
    extern __shared__ __align__(128) char sm[];
    const uint32_t smb = smem_u32(sm);
    const int mb = blockIdx.x;
    const int h = blockIdx.y;
    const int b = blockIdx.z;
    const int kvh = h >> 2;
    const int tid = threadIdx.x;
    const int warp = tid >> 5, lane = tid & 31;

    {
        const char* gqh = (const char*)(Qh + ((size_t)(b * SS + mb * 64)) * HIDN + h * HD);
        const char* gql = (const char*)(Ql + ((size_t)(b * SS + mb * 64)) * HIDN + h * HD);
#pragma unroll
        for (int t = 0; t < 8; ++t) {
            int id = tid + t * 128;
            int r = id >> 4;
            int cu = id & 15;
            cp16(smb + AT_Q_H + ASW(r, cu), gqh + (size_t)r * (HIDN * 2) + cu * 16);
            cp16(smb + AT_Q_L + ASW(r, cu), gql + (size_t)r * (HIDN * 2) + cu * 16);
        }
        cp_commit();
    }

    float o[16][4];
#pragma unroll
    for (int nt = 0; nt < 16; ++nt)
#pragma unroll
        for (int q = 0; q < 4; ++q) o[nt][q] = 0.f;
    float m_a = -INFINITY, m_b = -INFINITY, l_a = 0.f, l_b = 0.f;

    const int rowA = warp * 16 + (lane >> 2);
    const int grow_a = mb * 64 + rowA;
    const int grow_b = grow_a + 8;

    for (int nb = 0; nb <= mb; ++nb) {
        {
            const char* gkh = (const char*)(Kh + ((size_t)(b * SS + nb * 64)) * KVW + kvh * HD);
            const char* gkl = (const char*)(Kl + ((size_t)(b * SS + nb * 64)) * KVW + kvh * HD);
            const char* gvh = (const char*)(Vh + ((size_t)(b * SS + nb * 64)) * KVW + kvh * HD);
            const char* gvl = (const char*)(Vl + ((size_t)(b * SS + nb * 64)) * KVW + kvh * HD);
#pragma unroll
            for (int t = 0; t < 8; ++t) {
                int id = tid + t * 128;
                int r = id >> 4;
                int cu = id & 15;
                size_t go = (size_t)r * (KVW * 2) + cu * 16;
                uint32_t so = ASW(r, cu);
                cp16(smb + AT_K_H + so, gkh + go);
                cp16(smb + AT_K_L + so, gkl + go);
                cp16(smb + AT_V_H + so, gvh + go);
                cp16(smb + AT_V_L + so, gvl + go);
            }
            cp_commit();
            cp_wait<0>();
        }
        __syncthreads();

        float s[8][4];
#pragma unroll
        for (int j = 0; j < 8; ++j)
#pragma unroll
            for (int q = 0; q < 4; ++q) s[j][q] = 0.f;

#pragma unroll
        for (int ks = 0; ks < 8; ++ks) {
            uint32_t ah[4], al[4];
            {
                int r = warp * 16 + (lane & 15);
                int cu = ks * 2 + (lane >> 4);
                ldmx4(ah, smb + AT_Q_H + ASW(r, cu));
                ldmx4(al, smb + AT_Q_L + ASW(r, cu));
            }
#pragma unroll
            for (int j = 0; j < 8; ++j) {
                uint32_t bh[2], bl[2];
                int r = j * 8 + (lane & 7);
                int cu = ks * 2 + ((lane >> 3) & 1);
                ldmx2(bh, smb + AT_K_H + ASW(r, cu));
                ldmx2(bl, smb + AT_K_L + ASW(r, cu));
                mma_bf16(s[j], ah, bh);
                mma_bf16(s[j], ah, bl);
                mma_bf16(s[j], al, bh);
            }
        }

        if (nb == mb) {
#pragma unroll
            for (int j = 0; j < 8; ++j) {
                int col = nb * 64 + j * 8 + (lane & 3) * 2;
                if (col > grow_a)     s[j][0] = -1e30f;
                if (col + 1 > grow_a) s[j][1] = -1e30f;
                if (col > grow_b)     s[j][2] = -1e30f;
                if (col + 1 > grow_b) s[j][3] = -1e30f;
            }
        }

        float mx_a = -INFINITY, mx_b = -INFINITY;
#pragma unroll
        for (int j = 0; j < 8; ++j) {
            mx_a = fmaxf(mx_a, fmaxf(s[j][0], s[j][1]));
            mx_b = fmaxf(mx_b, fmaxf(s[j][2], s[j][3]));
        }
        mx_a = fmaxf(mx_a, __shfl_xor_sync(0xffffffffu, mx_a, 1));
        mx_a = fmaxf(mx_a, __shfl_xor_sync(0xffffffffu, mx_a, 2));
        mx_b = fmaxf(mx_b, __shfl_xor_sync(0xffffffffu, mx_b, 1));
        mx_b = fmaxf(mx_b, __shfl_xor_sync(0xffffffffu, mx_b, 2));

        float nm_a = fmaxf(m_a, mx_a);
        float nm_b = fmaxf(m_b, mx_b);
        float corr_a = __expf(m_a - nm_a);
        float corr_b = __expf(m_b - nm_b);
        m_a = nm_a; m_b = nm_b;

        float sum_a = 0.f, sum_b = 0.f;
#pragma unroll
        for (int j = 0; j < 8; ++j) {
            s[j][0] = __expf(s[j][0] - nm_a);
            s[j][1] = __expf(s[j][1] - nm_a);
            s[j][2] = __expf(s[j][2] - nm_b);
            s[j][3] = __expf(s[j][3] - nm_b);
            sum_a += s[j][0] + s[j][1];
            sum_b += s[j][2] + s[j][3];
        }
        sum_a += __shfl_xor_sync(0xffffffffu, sum_a, 1);
        sum_a += __shfl_xor_sync(0xffffffffu, sum_a, 2);
        sum_b += __shfl_xor_sync(0xffffffffu, sum_b, 1);
        sum_b += __shfl_xor_sync(0xffffffffu, sum_b, 2);
        l_a = l_a * corr_a + sum_a;
        l_b = l_b * corr_b + sum_b;

#pragma unroll
        for (int nt = 0; nt < 16; ++nt) {
            o[nt][0] *= corr_a; o[nt][1] *= corr_a;
            o[nt][2] *= corr_b; o[nt][3] *= corr_b;
        }

        uint32_t ph[4][4], pl[4][4];
#pragma unroll
        for (int ks = 0; ks < 4; ++ks) {
            const float* t0 = s[2 * ks];
            const float* t1 = s[2 * ks + 1];
            float v0[8] = {t0[0], t0[1], t0[2], t0[3], t1[0], t1[1], t1[2], t1[3]};
            uint16_t hb[8]; float rs[8];
#pragma unroll
            for (int e = 0; e < 8; ++e) {
                bf16 hh = __float2bfloat16(v0[e]);
                hb[e] = bfbits(hh);
                rs[e] = v0[e] - __bfloat162float(hh);
            }
            ph[ks][0] = ((uint32_t)hb[1] << 16) | hb[0];
            ph[ks][1] = ((uint32_t)hb[3] << 16) | hb[2];
            ph[ks][2] = ((uint32_t)hb[5] << 16) | hb[4];
            ph[ks][3] = ((uint32_t)hb[7] << 16) | hb[6];
            uint16_t lb[8];
#pragma unroll
            for (int e = 0; e < 8; ++e) lb[e] = bfbits(__float2bfloat16(rs[e]));
            pl[ks][0] = ((uint32_t)lb[1] << 16) | lb[0];
            pl[ks][1] = ((uint32_t)lb[3] << 16) | lb[2];
            pl[ks][2] = ((uint32_t)lb[5] << 16) | lb[4];
            pl[ks][3] = ((uint32_t)lb[7] << 16) | lb[6];
        }

#pragma unroll
        for (int nt = 0; nt < 16; ++nt) {
#pragma unroll
            for (int ks = 0; ks < 4; ++ks) {
                uint32_t bh[2], bl[2];
                int r = ks * 16 + (lane & 15);
                ldmx2t(bh, smb + AT_V_H + ASW(r, nt));
                ldmx2t(bl, smb + AT_V_L + ASW(r, nt));
                mma_bf16(o[nt], ph[ks], bh);
                mma_bf16(o[nt], ph[ks], bl);
                mma_bf16(o[nt], pl[ks], bh);
            }
        }
        __syncthreads();
    }

    const float inv_a = 1.f / l_a;
    const float inv_b = 1.f / l_b;
    const size_t ra = ((size_t)(b * SS + mb * 64 + rowA)) * HIDN + h * HD;
    const size_t rb = ra + (size_t)8 * HIDN;
#pragma unroll
    for (int nt = 0; nt < 16; ++nt) {
        int col = nt * 8 + (lane & 3) * 2;
        split_store(Ch, Cl, ra + col, o[nt][0] * inv_a, o[nt][1] * inv_a);
        split_store(Ch, Cl, rb + col, o[nt][2] * inv_b, o[nt][3] * inv_b);
    }
}

// ============================================================================
// Launch
// ============================================================================
extern "C" void kernel_launch(void* const* d_in, const int* in_sizes, int n_in,
                              void* d_out, int out_size)
{
    (void)in_sizes; (void)n_in; (void)out_size;
    const float* hs = (const float*)d_in[0];
    const float* Wq = (const float*)d_in[1];
    const float* Wk = (const float*)d_in[2];
    const float* Wv = (const float*)d_in[3];
    const float* Wo = (const float*)d_in[4];
    float* out = (float*)d_out;

    bf16 *hsh, *hsl, *wqh, *wql, *wkvh, *wkvl, *woh, *wol;
    bf16 *qh, *ql, *kh, *kl, *vh, *vl, *ch, *cl;
    cudaGetSymbolAddress((void**)&hsh, g_hs_h);   cudaGetSymbolAddress((void**)&hsl, g_hs_l);
    cudaGetSymbolAddress((void**)&wqh, g_wq_h);   cudaGetSymbolAddress((void**)&wql, g_wq_l);
    cudaGetSymbolAddress((void**)&wkvh, g_wkv_h); cudaGetSymbolAddress((void**)&wkvl, g_wkv_l);
    cudaGetSymbolAddress((void**)&woh, g_wo_h);   cudaGetSymbolAddress((void**)&wol, g_wo_l);
    cudaGetSymbolAddress((void**)&qh, g_qh);      cudaGetSymbolAddress((void**)&ql, g_ql);
    cudaGetSymbolAddress((void**)&kh, g_kh);      cudaGetSymbolAddress((void**)&kl, g_kl);
    cudaGetSymbolAddress((void**)&vh, g_vh);      cudaGetSymbolAddress((void**)&vl, g_vl);
    cudaGetSymbolAddress((void**)&ch, g_ch);      cudaGetSymbolAddress((void**)&cl, g_cl);

    cudaFuncSetAttribute(gemm_hmma<0>, cudaFuncAttributeMaxDynamicSharedMemorySize, GSM_BYTES);
    cudaFuncSetAttribute(gemm_hmma<1>, cudaFuncAttributeMaxDynamicSharedMemorySize, GSM_BYTES);
    cudaFuncSetAttribute(gemm_hmma<2>, cudaFuncAttributeMaxDynamicSharedMemorySize, GSM_BYTES);
    cudaFuncSetAttribute(attn_hmma, cudaFuncAttributeMaxDynamicSharedMemorySize, AT_SMEM);

    // 0: rope table
    rope_table<<<(SS * 64 + 255) / 256, 256>>>();
    // 1: all conversions in one kernel
    {
        size_t total = (size_t)MTOK * HIDN / 4 + 2 * (size_t)HIDN * HIDN / 4 + 2 * (size_t)KVW * HIDN / 4;
        cvt_all<<<(unsigned)((total + 255) / 256), 256>>>(hs, Wq, Wk, Wv, Wo);
    }
    // 2: Q projection (rope+scale+split fused)
    gemm_hmma<1><<<dim3(HIDN / 128, MTOK / 128), 256, GSM_BYTES>>>(hsh, hsl, wqh, wql, nullptr, MTOK, HIDN, HIDN);
    // 3: merged K|V projection
    gemm_hmma<2><<<dim3(2 * KVW / 128, MTOK / 128), 256, GSM_BYTES>>>(hsh, hsl, wkvh, wkvl, nullptr, MTOK, 2 * KVW, HIDN);
    // 4: attention
    attn_hmma<<<dim3(SS / 64, NH, BB), 128, AT_SMEM>>>(qh, ql, kh, kl, vh, vl, ch, cl);
    // 5: output projection
    gemm_hmma<0><<<dim3(HIDN / 128, MTOK / 128), 256, GSM_BYTES>>>(ch, cl, woh, wol, out, MTOK, HIDN, HIDN);
}

// round 12
// speedup vs baseline: 1.0186x; 1.0114x over previous
#include <cuda_runtime.h>
#include <cuda_bf16.h>
#include <math.h>
#include <stdint.h>

#define BB 2
#define SS 1024
#define HIDN 4096
#define NH 32
#define NKV 8
#define HD 128
#define MTOK (BB*SS)
#define KVW (NKV*HD)
#define NQKV (HIDN + 2*KVW)   // 6144 combined output columns
#define QSCALE 0.08838834764831845f

typedef __nv_bfloat16 bf16;

// ---------------- scratch ----------------
__device__ float g_rope[SS * 64 * 2];

__device__ bf16 g_hs_h[(size_t)MTOK * HIDN],   g_hs_l[(size_t)MTOK * HIDN];
__device__ bf16 g_wqkv_h[(size_t)NQKV * HIDN], g_wqkv_l[(size_t)NQKV * HIDN];
__device__ bf16 g_wo_h[(size_t)HIDN * HIDN],   g_wo_l[(size_t)HIDN * HIDN];

__device__ bf16 g_qh[(size_t)MTOK * HIDN], g_ql[(size_t)MTOK * HIDN];
__device__ bf16 g_kh[(size_t)MTOK * KVW],  g_kl[(size_t)MTOK * KVW];
__device__ bf16 g_vh[(size_t)MTOK * KVW],  g_vl[(size_t)MTOK * KVW];
__device__ bf16 g_ch[(size_t)MTOK * HIDN], g_cl[(size_t)MTOK * HIDN];

// ============================ helpers ====================================
__device__ __forceinline__ uint32_t smem_u32(const void* p) {
    uint32_t a;
    asm("{ .reg .u64 t; cvta.to.shared.u64 t, %1; cvt.u32.u64 %0, t; }" : "=r"(a) : "l"(p));
    return a;
}
__device__ __forceinline__ void cp16(uint32_t sdst, const void* gsrc) {
    asm volatile("cp.async.cg.shared.global [%0], [%1], 16;" :: "r"(sdst), "l"(gsrc));
}
__device__ __forceinline__ void cp_commit() {
    asm volatile("cp.async.commit_group;" ::: "memory");
}
template<int N> __device__ __forceinline__ void cp_wait() {
    asm volatile("cp.async.wait_group %0;" :: "n"(N) : "memory");
}
__device__ __forceinline__ void ldmx4(uint32_t* r, uint32_t addr) {
    asm volatile("ldmatrix.sync.aligned.m8n8.x4.shared.b16 {%0,%1,%2,%3}, [%4];"
                 : "=r"(r[0]), "=r"(r[1]), "=r"(r[2]), "=r"(r[3]) : "r"(addr));
}
__device__ __forceinline__ void ldmx2(uint32_t* r, uint32_t addr) {
    asm volatile("ldmatrix.sync.aligned.m8n8.x2.shared.b16 {%0,%1}, [%2];"
                 : "=r"(r[0]), "=r"(r[1]) : "r"(addr));
}
__device__ __forceinline__ void ldmx2t(uint32_t* r, uint32_t addr) {
    asm volatile("ldmatrix.sync.aligned.m8n8.x2.trans.shared.b16 {%0,%1}, [%2];"
                 : "=r"(r[0]), "=r"(r[1]) : "r"(addr));
}
__device__ __forceinline__ void mma_bf16(float* c, const uint32_t* a, const uint32_t* b) {
    asm volatile(
        "mma.sync.aligned.m16n8k16.row.col.f32.bf16.bf16.f32 "
        "{%0,%1,%2,%3}, {%4,%5,%6,%7}, {%8,%9}, {%0,%1,%2,%3};"
        : "+f"(c[0]), "+f"(c[1]), "+f"(c[2]), "+f"(c[3])
        : "r"(a[0]), "r"(a[1]), "r"(a[2]), "r"(a[3]), "r"(b[0]), "r"(b[1]));
}
__device__ __forceinline__ uint16_t bfbits(bf16 h) { return *(uint16_t*)&h; }

__device__ __forceinline__ void split_store(bf16* H, bf16* L, size_t idx, float a, float b) {
    bf16 h0 = __float2bfloat16(a);
    bf16 h1 = __float2bfloat16(b);
    bf16 l0 = __float2bfloat16(a - __bfloat162float(h0));
    bf16 l1 = __float2bfloat16(b - __bfloat162float(h1));
    uint32_t hp = ((uint32_t)bfbits(h1) << 16) | bfbits(h0);
    uint32_t lp = ((uint32_t)bfbits(l1) << 16) | bfbits(l0);
    *(uint32_t*)(H + idx) = hp;
    *(uint32_t*)(L + idx) = lp;
}

// ============================================================================
// Split-bf16 NT GEMM: EXACT round-8 proven core (256 thr, 2x4 warps, 128x128
// tile, BK=32, double-buffered cp.async, register-lean 3-group ordering,
// 2 CTAs/SM). EPI: 0 = fp32 store, 3 = merged QKV epilogue.
// ============================================================================
#define GBK 32
#define ROWB 80
#define ARR_B (128 * ROWB)
#define BUF_B (4 * ARR_B)
#define GSM_BYTES (2 * BUF_B)

template<int EPI>
__global__ __launch_bounds__(256, 2) void gemm_hmma(const bf16* __restrict__ Ah,
                                                    const bf16* __restrict__ Al,
                                                    const bf16* __restrict__ Bh,
                                                    const bf16* __restrict__ Bl,
                                                    float* __restrict__ Cf,
                                                    int M, int N, int K)
{
    extern __shared__ __align__(128) char sm[];
    const uint32_t smb = smem_u32(sm);
    const int tid = threadIdx.x;
    const int warp = tid >> 5, lane = tid & 31;
    const int wm = warp >> 2, wn = warp & 3;
    const int tn = blockIdx.x * 128;
    const int tm = blockIdx.y * 128;

    const char* gsrc[4];
    gsrc[0] = (const char*)(Ah + (size_t)tm * K);
    gsrc[1] = (const char*)(Al + (size_t)tm * K);
    gsrc[2] = (const char*)(Bh + (size_t)tn * K);
    gsrc[3] = (const char*)(Bl + (size_t)tn * K);
    const size_t rowb = (size_t)K * 2;

    float acc[4][4][4];
#pragma unroll
    for (int mt = 0; mt < 4; ++mt)
#pragma unroll
        for (int nt = 0; nt < 4; ++nt)
#pragma unroll
            for (int q = 0; q < 4; ++q) acc[mt][nt][q] = 0.f;

    const int nk = K / GBK;

    {
#pragma unroll
        for (int a4 = 0; a4 < 4; ++a4) {
#pragma unroll
            for (int i = 0; i < 2; ++i) {
                int id = tid + i * 256;
                int r = id >> 2;
                int c8 = id & 3;
                cp16(smb + a4 * ARR_B + r * ROWB + c8 * 16,
                     gsrc[a4] + (size_t)r * rowb + c8 * 16);
            }
        }
        cp_commit();
    }

    int buf = 0;
    for (int kc = 0; kc < nk; ++kc) {
        if (kc + 1 < nk) {
            const size_t coff = (size_t)(kc + 1) * 64;
            const uint32_t sb = smb + (buf ^ 1) * BUF_B;
#pragma unroll
            for (int a4 = 0; a4 < 4; ++a4) {
#pragma unroll
                for (int i = 0; i < 2; ++i) {
                    int id = tid + i * 256;
                    int r = id >> 2;
                    int c8 = id & 3;
                    cp16(sb + a4 * ARR_B + r * ROWB + c8 * 16,
                         gsrc[a4] + (size_t)r * rowb + coff + c8 * 16);
                }
            }
            cp_commit();
            cp_wait<1>();
        } else {
            cp_wait<0>();
        }
        __syncthreads();

        const uint32_t sAh = smb + buf * BUF_B + 0 * ARR_B;
        const uint32_t sAl = smb + buf * BUF_B + 1 * ARR_B;
        const uint32_t sBh = smb + buf * BUF_B + 2 * ARR_B;
        const uint32_t sBl = smb + buf * BUF_B + 3 * ARR_B;

#pragma unroll
        for (int ks = 0; ks < 2; ++ks) {
            uint32_t a[4][4], b[4][2], b2[4][2];
            const uint32_t acol = ks * 32 + (lane >> 4) * 16;
            const uint32_t bcol = ks * 32 + ((lane >> 3) & 1) * 16;
#pragma unroll
            for (int mt = 0; mt < 4; ++mt) {
                uint32_t roff = (uint32_t)(wm * 64 + mt * 16 + (lane & 15)) * ROWB + acol;
                ldmx4(a[mt], sAh + roff);
            }
#pragma unroll
            for (int nt = 0; nt < 4; ++nt) {
                uint32_t roff = (uint32_t)(wn * 32 + nt * 8 + (lane & 7)) * ROWB + bcol;
                ldmx2(b[nt], sBh + roff);
                ldmx2(b2[nt], sBl + roff);
            }
            // ah * bh
#pragma unroll
            for (int mt = 0; mt < 4; ++mt)
#pragma unroll
                for (int nt = 0; nt < 4; ++nt)
                    mma_bf16(acc[mt][nt], a[mt], b[nt]);
            // ah * bl
#pragma unroll
            for (int mt = 0; mt < 4; ++mt)
#pragma unroll
                for (int nt = 0; nt < 4; ++nt)
                    mma_bf16(acc[mt][nt], a[mt], b2[nt]);
            // al * bh (al overwrites a)
#pragma unroll
            for (int mt = 0; mt < 4; ++mt) {
                uint32_t roff = (uint32_t)(wm * 64 + mt * 16 + (lane & 15)) * ROWB + acol;
                ldmx4(a[mt], sAl + roff);
            }
#pragma unroll
            for (int mt = 0; mt < 4; ++mt)
#pragma unroll
                for (int nt = 0; nt < 4; ++nt)
                    mma_bf16(acc[mt][nt], a[mt], b[nt]);
        }
        __syncthreads();
        buf ^= 1;
    }

    // ---- epilogue ----
#pragma unroll
    for (int mt = 0; mt < 4; ++mt) {
        int row0 = tm + wm * 64 + mt * 16 + (lane >> 2);
#pragma unroll
        for (int nt = 0; nt < 4; ++nt) {
            int col = tn + wn * 32 + nt * 8 + (lane & 3) * 2;
            float c0 = acc[mt][nt][0], c1 = acc[mt][nt][1];
            float c2 = acc[mt][nt][2], c3 = acc[mt][nt][3];
            if (EPI == 0) {
                *(float2*)(Cf + (size_t)row0 * N + col) = make_float2(c0, c1);
                *(float2*)(Cf + (size_t)(row0 + 8) * N + col) = make_float2(c2, c3);
            } else {
                const int i = (col & 127) >> 1;
#pragma unroll
                for (int rr = 0; rr < 2; ++rr) {
                    int row = row0 + rr * 8;
                    float e = rr ? c2 : c0;
                    float o = rr ? c3 : c1;
                    int s = row & (SS - 1);
                    if (col < HIDN) {
                        // Q: rope + scale + split
                        float2 cs = *(const float2*)&g_rope[(s * 64 + i) * 2];
                        float oe = (e * cs.x - o * cs.y) * QSCALE;
                        float oo = (e * cs.y + o * cs.x) * QSCALE;
                        split_store(g_qh, g_ql, (size_t)row * HIDN + col, oe, oo);
                    } else if (col < HIDN + KVW) {
                        // K: rope + split
                        int c2i = col - HIDN;
                        float2 cs = *(const float2*)&g_rope[(s * 64 + i) * 2];
                        float oe = e * cs.x - o * cs.y;
                        float oo = e * cs.y + o * cs.x;
                        split_store(g_kh, g_kl, (size_t)row * KVW + c2i, oe, oo);
                    } else {
                        // V: split
                        int c2i = col - HIDN - KVW;
                        split_store(g_vh, g_vl, (size_t)row * KVW + c2i, e, o);
                    }
                }
            }
        }
    }
}

// ============================================================================
// One-shot conversion of hs + all weights into bf16 hi/lo (segmented).
// Wq/Wk/Wv land in the combined g_wqkv buffer.
// ============================================================================
__global__ void cvt_all(const float* __restrict__ hs, const float* __restrict__ Wq,
                        const float* __restrict__ Wk, const float* __restrict__ Wv,
                        const float* __restrict__ Wo)
{
    const size_t n_hs = (size_t)MTOK * HIDN / 4;
    const size_t n_wq = (size_t)HIDN * HIDN / 4;
    const size_t n_wk = (size_t)KVW * HIDN / 4;
    const size_t total = n_hs + n_wq + 2 * n_wk + n_wq;
    size_t i = (size_t)blockIdx.x * blockDim.x + threadIdx.x;
    if (i >= total) return;

    const float* src;
    bf16 *H, *L;
    size_t k;
    if (i < n_hs) {
        src = hs; H = g_hs_h; L = g_hs_l; k = i;
    } else if (i < n_hs + n_wq) {
        src = Wq; H = g_wqkv_h; L = g_wqkv_l; k = i - n_hs;
    } else if (i < n_hs + n_wq + n_wk) {
        src = Wk; k = i - n_hs - n_wq;
        H = g_wqkv_h + (size_t)HIDN * HIDN; L = g_wqkv_l + (size_t)HIDN * HIDN;
    } else if (i < n_hs + n_wq + 2 * n_wk) {
        src = Wv; k = i - n_hs - n_wq - n_wk;
        H = g_wqkv_h + (size_t)(HIDN + KVW) * HIDN; L = g_wqkv_l + (size_t)(HIDN + KVW) * HIDN;
    } else {
        src = Wo; H = g_wo_h; L = g_wo_l; k = i - n_hs - n_wq - 2 * n_wk;
    }

    float4 v = ((const float4*)src)[k];
    bf16 h[4], l[4];
    float x[4] = {v.x, v.y, v.z, v.w};
#pragma unroll
    for (int j = 0; j < 4; ++j) {
        h[j] = __float2bfloat16(x[j]);
        l[j] = __float2bfloat16(x[j] - __bfloat162float(h[j]));
    }
    *(uint2*)(H + k * 4) = *(uint2*)h;
    *(uint2*)(L + k * 4) = *(uint2*)l;
}

// ============================================================================
// RoPE table
// ============================================================================
__global__ void rope_table()
{
    int idx = blockIdx.x * blockDim.x + threadIdx.x;
    if (idx >= SS * 64) return;
    int s = idx >> 6, i = idx & 63;
    double inv = exp(-(double)i * (log(10000.0) / 64.0));
    double sn, cs;
    sincos((double)s * inv, &sn, &cs);
    g_rope[idx * 2 + 0] = (float)cs;
    g_rope[idx * 2 + 1] = (float)sn;
}

// ============================================================================
// HMMA flash attention (split bf16, 3-pass). K and V are loaded as SEPARATE
// cp.async groups: S=QK^T overlaps the V load. Epilogue writes split C.
// ============================================================================
#define ASW(row, colu) ((uint32_t)(row) * 256 + ((((uint32_t)(colu)) ^ ((row) & 7)) << 4))
#define AT_Q_H 0
#define AT_Q_L 16384
#define AT_K_H 32768
#define AT_K_L 49152
#define AT_V_H 65536
#define AT_V_L 81920
#define AT_SMEM 98304

__global__ __launch_bounds__(128) void attn_hmma(const bf16* __restrict__ Qh,
                                                 const bf16* __restrict__ Ql,
                                                 const bf16* __restrict__ Kh,
                                                 const bf16* __restrict__ Kl,
                                                 const bf16* __restrict__ Vh,
                                                 const bf16* __restrict__ Vl,
                                                 bf16* __restrict__ Ch,
                                                 bf16* __restrict__ Cl)
{
    extern __shared__ __align__(128) char sm[];
    const uint32_t smb = smem_u32(sm);
    const int mb = blockIdx.x;
    const int h = blockIdx.y;
    const int b = blockIdx.z;
    const int kvh = h >> 2;
    const int tid = threadIdx.x;
    const int warp = tid >> 5, lane = tid & 31;

    {
        const char* gqh = (const char*)(Qh + ((size_t)(b * SS + mb * 64)) * HIDN + h * HD);
        const char* gql = (const char*)(Ql + ((size_t)(b * SS + mb * 64)) * HIDN + h * HD);
#pragma unroll
        for (int t = 0; t < 8; ++t) {
            int id = tid + t * 128;
            int r = id >> 4;
            int cu = id & 15;
            cp16(smb + AT_Q_H + ASW(r, cu), gqh + (size_t)r * (HIDN * 2) + cu * 16);
            cp16(smb + AT_Q_L + ASW(r, cu), gql + (size_t)r * (HIDN * 2) + cu * 16);
        }
        cp_commit();
    }

    float o[16][4];
#pragma unroll
    for (int nt = 0; nt < 16; ++nt)
#pragma unroll
        for (int q = 0; q < 4; ++q) o[nt][q] = 0.f;
    float m_a = -INFINITY, m_b = -INFINITY, l_a = 0.f, l_b = 0.f;

    const int rowA = warp * 16 + (lane >> 2);
    const int grow_a = mb * 64 + rowA;
    const int grow_b = grow_a + 8;

    for (int nb = 0; nb <= mb; ++nb) {
        // ---- K group, then V group (separate commits) ----
        {
            const char* gkh = (const char*)(Kh + ((size_t)(b * SS + nb * 64)) * KVW + kvh * HD);
            const char* gkl = (const char*)(Kl + ((size_t)(b * SS + nb * 64)) * KVW + kvh * HD);
#pragma unroll
            for (int t = 0; t < 8; ++t) {
                int id = tid + t * 128;
                int r = id >> 4;
                int cu = id & 15;
                size_t go = (size_t)r * (KVW * 2) + cu * 16;
                uint32_t so = ASW(r, cu);
                cp16(smb + AT_K_H + so, gkh + go);
                cp16(smb + AT_K_L + so, gkl + go);
            }
            cp_commit();
            const char* gvh = (const char*)(Vh + ((size_t)(b * SS + nb * 64)) * KVW + kvh * HD);
            const char* gvl = (const char*)(Vl + ((size_t)(b * SS + nb * 64)) * KVW + kvh * HD);
#pragma unroll
            for (int t = 0; t < 8; ++t) {
                int id = tid + t * 128;
                int r = id >> 4;
                int cu = id & 15;
                size_t go = (size_t)r * (KVW * 2) + cu * 16;
                uint32_t so = ASW(r, cu);
                cp16(smb + AT_V_H + so, gvh + go);
                cp16(smb + AT_V_L + so, gvl + go);
            }
            cp_commit();
            cp_wait<1>();   // Q + K complete; V may still be in flight
        }
        __syncthreads();

        float s[8][4];
#pragma unroll
        for (int j = 0; j < 8; ++j)
#pragma unroll
            for (int q = 0; q < 4; ++q) s[j][q] = 0.f;

#pragma unroll
        for (int ks = 0; ks < 8; ++ks) {
            uint32_t ah[4], al[4];
            {
                int r = warp * 16 + (lane & 15);
                int cu = ks * 2 + (lane >> 4);
                ldmx4(ah, smb + AT_Q_H + ASW(r, cu));
                ldmx4(al, smb + AT_Q_L + ASW(r, cu));
            }
#pragma unroll
            for (int j = 0; j < 8; ++j) {
                uint32_t bh[2], bl[2];
                int r = j * 8 + (lane & 7);
                int cu = ks * 2 + ((lane >> 3) & 1);
                ldmx2(bh, smb + AT_K_H + ASW(r, cu));
                ldmx2(bl, smb + AT_K_L + ASW(r, cu));
                mma_bf16(s[j], ah, bh);
                mma_bf16(s[j], ah, bl);
                mma_bf16(s[j], al, bh);
            }
        }

        if (nb == mb) {
#pragma unroll
            for (int j = 0; j < 8; ++j) {
                int col = nb * 64 + j * 8 + (lane & 3) * 2;
                if (col > grow_a)     s[j][0] = -1e30f;
                if (col + 1 > grow_a) s[j][1] = -1e30f;
                if (col > grow_b)     s[j][2] = -1e30f;
                if (col + 1 > grow_b) s[j][3] = -1e30f;
            }
        }

        float mx_a = -INFINITY, mx_b = -INFINITY;
#pragma unroll
        for (int j = 0; j < 8; ++j) {
            mx_a = fmaxf(mx_a, fmaxf(s[j][0], s[j][1]));
            mx_b = fmaxf(mx_b, fmaxf(s[j][2], s[j][3]));
        }
        mx_a = fmaxf(mx_a, __shfl_xor_sync(0xffffffffu, mx_a, 1));
        mx_a = fmaxf(mx_a, __shfl_xor_sync(0xffffffffu, mx_a, 2));
        mx_b = fmaxf(mx_b, __shfl_xor_sync(0xffffffffu, mx_b, 1));
        mx_b = fmaxf(mx_b, __shfl_xor_sync(0xffffffffu, mx_b, 2));

        float nm_a = fmaxf(m_a, mx_a);
        float nm_b = fmaxf(m_b, mx_b);
        float corr_a = __expf(m_a - nm_a);
        float corr_b = __expf(m_b - nm_b);
        m_a = nm_a; m_b = nm_b;

        float sum_a = 0.f, sum_b = 0.f;
#pragma unroll
        for (int j = 0; j < 8; ++j) {
            s[j][0] = __expf(s[j][0] - nm_a);
            s[j][1] = __expf(s[j][1] - nm_a);
            s[j][2] = __expf(s[j][2] - nm_b);
            s[j][3] = __expf(s[j][3] - nm_b);
            sum_a += s[j][0] + s[j][1];
            sum_b += s[j][2] + s[j][3];
        }
        sum_a += __shfl_xor_sync(0xffffffffu, sum_a, 1);
        sum_a += __shfl_xor_sync(0xffffffffu, sum_a, 2);
        sum_b += __shfl_xor_sync(0xffffffffu, sum_b, 1);
        sum_b += __shfl_xor_sync(0xffffffffu, sum_b, 2);
        l_a = l_a * corr_a + sum_a;
        l_b = l_b * corr_b + sum_b;

#pragma unroll
        for (int nt = 0; nt < 16; ++nt) {
            o[nt][0] *= corr_a; o[nt][1] *= corr_a;
            o[nt][2] *= corr_b; o[nt][3] *= corr_b;
        }

        uint32_t ph[4][4], pl[4][4];
#pragma unroll
        for (int ks = 0; ks < 4; ++ks) {
            const float* t0 = s[2 * ks];
            const float* t1 = s[2 * ks + 1];
            float v0[8] = {t0[0], t0[1], t0[2], t0[3], t1[0], t1[1], t1[2], t1[3]};
            uint16_t hb[8]; float rs[8];
#pragma unroll
            for (int e = 0; e < 8; ++e) {
                bf16 hh = __float2bfloat16(v0[e]);
                hb[e] = bfbits(hh);
                rs[e] = v0[e] - __bfloat162float(hh);
            }
            ph[ks][0] = ((uint32_t)hb[1] << 16) | hb[0];
            ph[ks][1] = ((uint32_t)hb[3] << 16) | hb[2];
            ph[ks][2] = ((uint32_t)hb[5] << 16) | hb[4];
            ph[ks][3] = ((uint32_t)hb[7] << 16) | hb[6];
            uint16_t lb[8];
#pragma unroll
            for (int e = 0; e < 8; ++e) lb[e] = bfbits(__float2bfloat16(rs[e]));
            pl[ks][0] = ((uint32_t)lb[1] << 16) | lb[0];
            pl[ks][1] = ((uint32_t)lb[3] << 16) | lb[2];
            pl[ks][2] = ((uint32_t)lb[5] << 16) | lb[4];
            pl[ks][3] = ((uint32_t)lb[7] << 16) | lb[6];
        }

        // V must be resident now
        cp_wait<0>();
        __syncthreads();

#pragma unroll
        for (int nt = 0; nt < 16; ++nt) {
#pragma unroll
            for (int ks = 0; ks < 4; ++ks) {
                uint32_t bh[2], bl[2];
                int r = ks * 16 + (lane & 15);
                ldmx2t(bh, smb + AT_V_H + ASW(r, nt));
                ldmx2t(bl, smb + AT_V_L + ASW(r, nt));
                mma_bf16(o[nt], ph[ks], bh);
                mma_bf16(o[nt], ph[ks], bl);
                mma_bf16(o[nt], pl[ks], bh);
            }
        }
        __syncthreads();
    }

    const float inv_a = 1.f / l_a;
    const float inv_b = 1.f / l_b;
    const size_t ra = ((size_t)(b * SS + mb * 64 + rowA)) * HIDN + h * HD;
    const size_t rb = ra + (size_t)8 * HIDN;
#pragma unroll
    for (int nt = 0; nt < 16; ++nt) {
        int col = nt * 8 + (lane & 3) * 2;
        split_store(Ch, Cl, ra + col, o[nt][0] * inv_a, o[nt][1] * inv_a);
        split_store(Ch, Cl, rb + col, o[nt][2] * inv_b, o[nt][3] * inv_b);
    }
}

// ============================================================================
// Launch
// ============================================================================
extern "C" void kernel_launch(void* const* d_in, const int* in_sizes, int n_in,
                              void* d_out, int out_size)
{
    (void)in_sizes; (void)n_in; (void)out_size;
    const float* hs = (const float*)d_in[0];
    const float* Wq = (const float*)d_in[1];
    const float* Wk = (const float*)d_in[2];
    const float* Wv = (const float*)d_in[3];
    const float* Wo = (const float*)d_in[4];
    float* out = (float*)d_out;

    bf16 *hsh, *hsl, *wqkvh, *wqkvl, *woh, *wol;
    bf16 *qh, *ql, *kh, *kl, *vh, *vl, *ch, *cl;
    cudaGetSymbolAddress((void**)&hsh, g_hs_h);     cudaGetSymbolAddress((void**)&hsl, g_hs_l);
    cudaGetSymbolAddress((void**)&wqkvh, g_wqkv_h); cudaGetSymbolAddress((void**)&wqkvl, g_wqkv_l);
    cudaGetSymbolAddress((void**)&woh, g_wo_h);     cudaGetSymbolAddress((void**)&wol, g_wo_l);
    cudaGetSymbolAddress((void**)&qh, g_qh);        cudaGetSymbolAddress((void**)&ql, g_ql);
    cudaGetSymbolAddress((void**)&kh, g_kh);        cudaGetSymbolAddress((void**)&kl, g_kl);
    cudaGetSymbolAddress((void**)&vh, g_vh);        cudaGetSymbolAddress((void**)&vl, g_vl);
    cudaGetSymbolAddress((void**)&ch, g_ch);        cudaGetSymbolAddress((void**)&cl, g_cl);

    cudaFuncSetAttribute(gemm_hmma<0>, cudaFuncAttributeMaxDynamicSharedMemorySize, GSM_BYTES);
    cudaFuncSetAttribute(gemm_hmma<3>, cudaFuncAttributeMaxDynamicSharedMemorySize, GSM_BYTES);
    cudaFuncSetAttribute(attn_hmma, cudaFuncAttributeMaxDynamicSharedMemorySize, AT_SMEM);

    // 0: rope table
    rope_table<<<(SS * 64 + 255) / 256, 256>>>();
    // 1: all conversions in one kernel
    {
        size_t total = (size_t)MTOK * HIDN / 4 + 2 * (size_t)HIDN * HIDN / 4 + 2 * (size_t)KVW * HIDN / 4;
        cvt_all<<<(unsigned)((total + 255) / 256), 256>>>(hs, Wq, Wk, Wv, Wo);
    }
    // 2: merged Q|K|V projection (fused rope/scale/split epilogues)
    gemm_hmma<3><<<dim3(NQKV / 128, MTOK / 128), 256, GSM_BYTES>>>(hsh, hsl, wqkvh, wqkvl, nullptr, MTOK, NQKV, HIDN);
    // 3: attention (K/V split-group overlap)
    attn_hmma<<<dim3(SS / 64, NH, BB), 128, AT_SMEM>>>(qh, ql, kh, kl, vh, vl, ch, cl);
    // 4: output projection
    gemm_hmma<0><<<dim3(HIDN / 128, MTOK / 128), 256, GSM_BYTES>>>(ch, cl, woh, wol, out, MTOK, HIDN, HIDN);
}

// round 17
// speedup vs baseline: 1.2182x; 1.1960x over previous
#include <cuda_runtime.h>
#include <cuda_bf16.h>
#include <math.h>
#include <stdint.h>

#define BB 2
#define SS 1024
#define HIDN 4096
#define NH 32
#define NKV 8
#define HD 128
#define MTOK (BB*SS)
#define KVW (NKV*HD)
#define NQKV (HIDN + 2*KVW)   // 6144 combined output columns
#define QSCALE 0.08838834764831845f

typedef __nv_bfloat16 bf16;

// ---------------- scratch ----------------
__device__ float g_rope[SS * 64 * 2];

__device__ bf16 g_hs_h[(size_t)MTOK * HIDN],   g_hs_l[(size_t)MTOK * HIDN];
__device__ bf16 g_wqkv_h[(size_t)NQKV * HIDN], g_wqkv_l[(size_t)NQKV * HIDN];
__device__ bf16 g_wo_h[(size_t)HIDN * HIDN],   g_wo_l[(size_t)HIDN * HIDN];

__device__ bf16 g_qh[(size_t)MTOK * HIDN], g_ql[(size_t)MTOK * HIDN];
__device__ bf16 g_kh[(size_t)MTOK * KVW],  g_kl[(size_t)MTOK * KVW];
__device__ bf16 g_vh[(size_t)MTOK * KVW],  g_vl[(size_t)MTOK * KVW];
__device__ bf16 g_ch[(size_t)MTOK * HIDN], g_cl[(size_t)MTOK * HIDN];

// ============================ helpers ====================================
__device__ __forceinline__ uint32_t smem_u32(const void* p) {
    uint32_t a;
    asm("{ .reg .u64 t; cvta.to.shared.u64 t, %1; cvt.u32.u64 %0, t; }" : "=r"(a) : "l"(p));
    return a;
}
__device__ __forceinline__ void cp16(uint32_t sdst, const void* gsrc) {
    asm volatile("cp.async.cg.shared.global [%0], [%1], 16;" :: "r"(sdst), "l"(gsrc));
}
__device__ __forceinline__ void cp_commit() {
    asm volatile("cp.async.commit_group;" ::: "memory");
}
template<int N> __device__ __forceinline__ void cp_wait() {
    asm volatile("cp.async.wait_group %0;" :: "n"(N) : "memory");
}
__device__ __forceinline__ void ldmx4(uint32_t* r, uint32_t addr) {
    asm volatile("ldmatrix.sync.aligned.m8n8.x4.shared.b16 {%0,%1,%2,%3}, [%4];"
                 : "=r"(r[0]), "=r"(r[1]), "=r"(r[2]), "=r"(r[3]) : "r"(addr));
}
__device__ __forceinline__ void ldmx2(uint32_t* r, uint32_t addr) {
    asm volatile("ldmatrix.sync.aligned.m8n8.x2.shared.b16 {%0,%1}, [%2];"
                 : "=r"(r[0]), "=r"(r[1]) : "r"(addr));
}
__device__ __forceinline__ void ldmx2t(uint32_t* r, uint32_t addr) {
    asm volatile("ldmatrix.sync.aligned.m8n8.x2.trans.shared.b16 {%0,%1}, [%2];"
                 : "=r"(r[0]), "=r"(r[1]) : "r"(addr));
}
__device__ __forceinline__ void mma_bf16(float* c, const uint32_t* a, const uint32_t* b) {
    asm volatile(
        "mma.sync.aligned.m16n8k16.row.col.f32.bf16.bf16.f32 "
        "{%0,%1,%2,%3}, {%4,%5,%6,%7}, {%8,%9}, {%0,%1,%2,%3};"
        : "+f"(c[0]), "+f"(c[1]), "+f"(c[2]), "+f"(c[3])
        : "r"(a[0]), "r"(a[1]), "r"(a[2]), "r"(a[3]), "r"(b[0]), "r"(b[1]));
}
__device__ __forceinline__ uint16_t bfbits(bf16 h) { return *(uint16_t*)&h; }

__device__ __forceinline__ void split_store(bf16* H, bf16* L, size_t idx, float a, float b) {
    bf16 h0 = __float2bfloat16(a);
    bf16 h1 = __float2bfloat16(b);
    bf16 l0 = __float2bfloat16(a - __bfloat162float(h0));
    bf16 l1 = __float2bfloat16(b - __bfloat162float(h1));
    uint32_t hp = ((uint32_t)bfbits(h1) << 16) | bfbits(h0);
    uint32_t lp = ((uint32_t)bfbits(l1) << 16) | bfbits(l0);
    *(uint32_t*)(H + idx) = hp;
    *(uint32_t*)(L + idx) = lp;
}

// ============================================================================
// Split-bf16 NT GEMM: round-8 proven core (256 thr, 2x4 warps, 128x128 tile,
// BK=32, double-buffered cp.async, register-lean 3-group ordering, 2 CTAs/SM)
// with SINGLE-sync mid-chunk prefetch schedule:
//   loop: wait<0>; sync; [ks=0]; issue(kc+1 -> buf^1); commit; [ks=1]
// Safety: the top sync of chunk kc guarantees all warps finished kc-1 (so the
// mid-chunk issue into buf^1 cannot race kc-1 readers of buf^1), and provides
// cross-thread visibility of group kc after wait<0>.
// EPI: 0 = fp32 store, 3 = merged QKV epilogue.
// ============================================================================
#define GBK 32
#define ROWB 80
#define ARR_B (128 * ROWB)
#define BUF_B (4 * ARR_B)
#define GSM_BYTES (2 * BUF_B)

template<int EPI>
__global__ __launch_bounds__(256, 2) void gemm_hmma(const bf16* __restrict__ Ah,
                                                    const bf16* __restrict__ Al,
                                                    const bf16* __restrict__ Bh,
                                                    const bf16* __restrict__ Bl,
                                                    float* __restrict__ Cf,
                                                    int M, int N, int K)
{
    extern __shared__ __align__(128) char sm[];
    const uint32_t smb = smem_u32(sm);
    const int tid = threadIdx.x;
    const int warp = tid >> 5, lane = tid & 31;
    const int wm = warp >> 2, wn = warp & 3;
    const int tn = blockIdx.x * 128;
    const int tm = blockIdx.y * 128;

    const char* gsrc[4];
    gsrc[0] = (const char*)(Ah + (size_t)tm * K);
    gsrc[1] = (const char*)(Al + (size_t)tm * K);
    gsrc[2] = (const char*)(Bh + (size_t)tn * K);
    gsrc[3] = (const char*)(Bl + (size_t)tn * K);
    const size_t rowb = (size_t)K * 2;

    float acc[4][4][4];
#pragma unroll
    for (int mt = 0; mt < 4; ++mt)
#pragma unroll
        for (int nt = 0; nt < 4; ++nt)
#pragma unroll
            for (int q = 0; q < 4; ++q) acc[mt][nt][q] = 0.f;

    const int nk = K / GBK;

    // prologue: chunk 0 -> buffer 0 (one group in flight)
    {
#pragma unroll
        for (int a4 = 0; a4 < 4; ++a4) {
#pragma unroll
            for (int i = 0; i < 2; ++i) {
                int id = tid + i * 256;
                int r = id >> 2;
                int c8 = id & 3;
                cp16(smb + a4 * ARR_B + r * ROWB + c8 * 16,
                     gsrc[a4] + (size_t)r * rowb + c8 * 16);
            }
        }
        cp_commit();
    }

    int buf = 0;
    for (int kc = 0; kc < nk; ++kc) {
        cp_wait<0>();      // group kc complete (only pending group)
        __syncthreads();   // visibility + all warps finished chunk kc-1

        const uint32_t sAh = smb + buf * BUF_B + 0 * ARR_B;
        const uint32_t sAl = smb + buf * BUF_B + 1 * ARR_B;
        const uint32_t sBh = smb + buf * BUF_B + 2 * ARR_B;
        const uint32_t sBl = smb + buf * BUF_B + 3 * ARR_B;

#pragma unroll
        for (int ks = 0; ks < 2; ++ks) {
            uint32_t a[4][4], b[4][2], b2[4][2];
            const uint32_t acol = ks * 32 + (lane >> 4) * 16;
            const uint32_t bcol = ks * 32 + ((lane >> 3) & 1) * 16;
#pragma unroll
            for (int mt = 0; mt < 4; ++mt) {
                uint32_t roff = (uint32_t)(wm * 64 + mt * 16 + (lane & 15)) * ROWB + acol;
                ldmx4(a[mt], sAh + roff);
            }
#pragma unroll
            for (int nt = 0; nt < 4; ++nt) {
                uint32_t roff = (uint32_t)(wn * 32 + nt * 8 + (lane & 7)) * ROWB + bcol;
                ldmx2(b[nt], sBh + roff);
                ldmx2(b2[nt], sBl + roff);
            }
            // ah * bh
#pragma unroll
            for (int mt = 0; mt < 4; ++mt)
#pragma unroll
                for (int nt = 0; nt < 4; ++nt)
                    mma_bf16(acc[mt][nt], a[mt], b[nt]);
            // ah * bl
#pragma unroll
            for (int mt = 0; mt < 4; ++mt)
#pragma unroll
                for (int nt = 0; nt < 4; ++nt)
                    mma_bf16(acc[mt][nt], a[mt], b2[nt]);
            // al * bh (al overwrites a)
#pragma unroll
            for (int mt = 0; mt < 4; ++mt) {
                uint32_t roff = (uint32_t)(wm * 64 + mt * 16 + (lane & 15)) * ROWB + acol;
                ldmx4(a[mt], sAl + roff);
            }
#pragma unroll
            for (int mt = 0; mt < 4; ++mt)
#pragma unroll
                for (int nt = 0; nt < 4; ++nt)
                    mma_bf16(acc[mt][nt], a[mt], b[nt]);

            // mid-chunk prefetch: after ks=0 compute, issue chunk kc+1 -> buf^1
            if (ks == 0 && kc + 1 < nk) {
                const size_t coff = (size_t)(kc + 1) * 64;
                const uint32_t sb = smb + (buf ^ 1) * BUF_B;
#pragma unroll
                for (int a4 = 0; a4 < 4; ++a4) {
#pragma unroll
                    for (int i = 0; i < 2; ++i) {
                        int id = tid + i * 256;
                        int r = id >> 2;
                        int c8 = id & 3;
                        cp16(sb + a4 * ARR_B + r * ROWB + c8 * 16,
                             gsrc[a4] + (size_t)r * rowb + coff + c8 * 16);
                    }
                }
                cp_commit();
            }
        }
        buf ^= 1;
    }

    // ---- epilogue ----
#pragma unroll
    for (int mt = 0; mt < 4; ++mt) {
        int row0 = tm + wm * 64 + mt * 16 + (lane >> 2);
#pragma unroll
        for (int nt = 0; nt < 4; ++nt) {
            int col = tn + wn * 32 + nt * 8 + (lane & 3) * 2;
            float c0 = acc[mt][nt][0], c1 = acc[mt][nt][1];
            float c2 = acc[mt][nt][2], c3 = acc[mt][nt][3];
            if (EPI == 0) {
                *(float2*)(Cf + (size_t)row0 * N + col) = make_float2(c0, c1);
                *(float2*)(Cf + (size_t)(row0 + 8) * N + col) = make_float2(c2, c3);
            } else {
                const int i = (col & 127) >> 1;
#pragma unroll
                for (int rr = 0; rr < 2; ++rr) {
                    int row = row0 + rr * 8;
                    float e = rr ? c2 : c0;
                    float o = rr ? c3 : c1;
                    int s = row & (SS - 1);
                    if (col < HIDN) {
                        float2 cs = *(const float2*)&g_rope[(s * 64 + i) * 2];
                        float oe = (e * cs.x - o * cs.y) * QSCALE;
                        float oo = (e * cs.y + o * cs.x) * QSCALE;
                        split_store(g_qh, g_ql, (size_t)row * HIDN + col, oe, oo);
                    } else if (col < HIDN + KVW) {
                        int c2i = col - HIDN;
                        float2 cs = *(const float2*)&g_rope[(s * 64 + i) * 2];
                        float oe = e * cs.x - o * cs.y;
                        float oo = e * cs.y + o * cs.x;
                        split_store(g_kh, g_kl, (size_t)row * KVW + c2i, oe, oo);
                    } else {
                        int c2i = col - HIDN - KVW;
                        split_store(g_vh, g_vl, (size_t)row * KVW + c2i, e, o);
                    }
                }
            }
        }
    }
}

// ============================================================================
// One-shot conversion of hs + all weights into bf16 hi/lo (segmented).
// ============================================================================
__global__ void cvt_all(const float* __restrict__ hs, const float* __restrict__ Wq,
                        const float* __restrict__ Wk, const float* __restrict__ Wv,
                        const float* __restrict__ Wo)
{
    const size_t n_hs = (size_t)MTOK * HIDN / 4;
    const size_t n_wq = (size_t)HIDN * HIDN / 4;
    const size_t n_wk = (size_t)KVW * HIDN / 4;
    const size_t total = n_hs + n_wq + 2 * n_wk + n_wq;
    size_t i = (size_t)blockIdx.x * blockDim.x + threadIdx.x;
    if (i >= total) return;

    const float* src;
    bf16 *H, *L;
    size_t k;
    if (i < n_hs) {
        src = hs; H = g_hs_h; L = g_hs_l; k = i;
    } else if (i < n_hs + n_wq) {
        src = Wq; H = g_wqkv_h; L = g_wqkv_l; k = i - n_hs;
    } else if (i < n_hs + n_wq + n_wk) {
        src = Wk; k = i - n_hs - n_wq;
        H = g_wqkv_h + (size_t)HIDN * HIDN; L = g_wqkv_l + (size_t)HIDN * HIDN;
    } else if (i < n_hs + n_wq + 2 * n_wk) {
        src = Wv; k = i - n_hs - n_wq - n_wk;
        H = g_wqkv_h + (size_t)(HIDN + KVW) * HIDN; L = g_wqkv_l + (size_t)(HIDN + KVW) * HIDN;
    } else {
        src = Wo; H = g_wo_h; L = g_wo_l; k = i - n_hs - n_wq - 2 * n_wk;
    }

    float4 v = ((const float4*)src)[k];
    bf16 h[4], l[4];
    float x[4] = {v.x, v.y, v.z, v.w};
#pragma unroll
    for (int j = 0; j < 4; ++j) {
        h[j] = __float2bfloat16(x[j]);
        l[j] = __float2bfloat16(x[j] - __bfloat162float(h[j]));
    }
    *(uint2*)(H + k * 4) = *(uint2*)h;
    *(uint2*)(L + k * 4) = *(uint2*)l;
}

// ============================================================================
// RoPE table
// ============================================================================
__global__ void rope_table()
{
    int idx = blockIdx.x * blockDim.x + threadIdx.x;
    if (idx >= SS * 64) return;
    int s = idx >> 6, i = idx & 63;
    double inv = exp(-(double)i * (log(10000.0) / 64.0));
    double sn, cs;
    sincos((double)s * inv, &sn, &cs);
    g_rope[idx * 2 + 0] = (float)cs;
    g_rope[idx * 2 + 1] = (float)sn;
}

// ============================================================================
// HMMA flash attention (split bf16, 3-pass). K and V loaded as SEPARATE
// cp.async groups so S=QK^T overlaps the V load. Epilogue writes split C.
// ============================================================================
#define ASW(row, colu) ((uint32_t)(row) * 256 + ((((uint32_t)(colu)) ^ ((row) & 7)) << 4))
#define AT_Q_H 0
#define AT_Q_L 16384
#define AT_K_H 32768
#define AT_K_L 49152
#define AT_V_H 65536
#define AT_V_L 81920
#define AT_SMEM 98304

__global__ __launch_bounds__(128) void attn_hmma(const bf16* __restrict__ Qh,
                                                 const bf16* __restrict__ Ql,
                                                 const bf16* __restrict__ Kh,
                                                 const bf16* __restrict__ Kl,
                                                 const bf16* __restrict__ Vh,
                                                 const bf16* __restrict__ Vl,
                                                 bf16* __restrict__ Ch,
                                                 bf16* __restrict__ Cl)
{
    extern __shared__ __align__(128) char sm[];
    const uint32_t smb = smem_u32(sm);
    const int mb = blockIdx.x;
    const int h = blockIdx.y;
    const int b = blockIdx.z;
    const int kvh = h >> 2;
    const int tid = threadIdx.x;
    const int warp = tid >> 5, lane = tid & 31;

    {
        const char* gqh = (const char*)(Qh + ((size_t)(b * SS + mb * 64)) * HIDN + h * HD);
        const char* gql = (const char*)(Ql + ((size_t)(b * SS + mb * 64)) * HIDN + h * HD);
#pragma unroll
        for (int t = 0; t < 8; ++t) {
            int id = tid + t * 128;
            int r = id >> 4;
            int cu = id & 15;
            cp16(smb + AT_Q_H + ASW(r, cu), gqh + (size_t)r * (HIDN * 2) + cu * 16);
            cp16(smb + AT_Q_L + ASW(r, cu), gql + (size_t)r * (HIDN * 2) + cu * 16);
        }
        cp_commit();
    }

    float o[16][4];
#pragma unroll
    for (int nt = 0; nt < 16; ++nt)
#pragma unroll
        for (int q = 0; q < 4; ++q) o[nt][q] = 0.f;
    float m_a = -INFINITY, m_b = -INFINITY, l_a = 0.f, l_b = 0.f;

    const int rowA = warp * 16 + (lane >> 2);
    const int grow_a = mb * 64 + rowA;
    const int grow_b = grow_a + 8;

    for (int nb = 0; nb <= mb; ++nb) {
        {
            const char* gkh = (const char*)(Kh + ((size_t)(b * SS + nb * 64)) * KVW + kvh * HD);
            const char* gkl = (const char*)(Kl + ((size_t)(b * SS + nb * 64)) * KVW + kvh * HD);
#pragma unroll
            for (int t = 0; t < 8; ++t) {
                int id = tid + t * 128;
                int r = id >> 4;
                int cu = id & 15;
                size_t go = (size_t)r * (KVW * 2) + cu * 16;
                uint32_t so = ASW(r, cu);
                cp16(smb + AT_K_H + so, gkh + go);
                cp16(smb + AT_K_L + so, gkl + go);
            }
            cp_commit();
            const char* gvh = (const char*)(Vh + ((size_t)(b * SS + nb * 64)) * KVW + kvh * HD);
            const char* gvl = (const char*)(Vl + ((size_t)(b * SS + nb * 64)) * KVW + kvh * HD);
#pragma unroll
            for (int t = 0; t < 8; ++t) {
                int id = tid + t * 128;
                int r = id >> 4;
                int cu = id & 15;
                size_t go = (size_t)r * (KVW * 2) + cu * 16;
                uint32_t so = ASW(r, cu);
                cp16(smb + AT_V_H + so, gvh + go);
                cp16(smb + AT_V_L + so, gvl + go);
            }
            cp_commit();
            cp_wait<1>();   // Q + K complete; V may still be in flight
        }
        __syncthreads();

        float s[8][4];
#pragma unroll
        for (int j = 0; j < 8; ++j)
#pragma unroll
            for (int q = 0; q < 4; ++q) s[j][q] = 0.f;

#pragma unroll
        for (int ks = 0; ks < 8; ++ks) {
            uint32_t ah[4], al[4];
            {
                int r = warp * 16 + (lane & 15);
                int cu = ks * 2 + (lane >> 4);
                ldmx4(ah, smb + AT_Q_H + ASW(r, cu));
                ldmx4(al, smb + AT_Q_L + ASW(r, cu));
            }
#pragma unroll
            for (int j = 0; j < 8; ++j) {
                uint32_t bh[2], bl[2];
                int r = j * 8 + (lane & 7);
                int cu = ks * 2 + ((lane >> 3) & 1);
                ldmx2(bh, smb + AT_K_H + ASW(r, cu));
                ldmx2(bl, smb + AT_K_L + ASW(r, cu));
                mma_bf16(s[j], ah, bh);
                mma_bf16(s[j], ah, bl);
                mma_bf16(s[j], al, bh);
            }
        }

        if (nb == mb) {
#pragma unroll
            for (int j = 0; j < 8; ++j) {
                int col = nb * 64 + j * 8 + (lane & 3) * 2;
                if (col > grow_a)     s[j][0] = -1e30f;
                if (col + 1 > grow_a) s[j][1] = -1e30f;
                if (col > grow_b)     s[j][2] = -1e30f;
                if (col + 1 > grow_b) s[j][3] = -1e30f;
            }
        }

        float mx_a = -INFINITY, mx_b = -INFINITY;
#pragma unroll
        for (int j = 0; j < 8; ++j) {
            mx_a = fmaxf(mx_a, fmaxf(s[j][0], s[j][1]));
            mx_b = fmaxf(mx_b, fmaxf(s[j][2], s[j][3]));
        }
        mx_a = fmaxf(mx_a, __shfl_xor_sync(0xffffffffu, mx_a, 1));
        mx_a = fmaxf(mx_a, __shfl_xor_sync(0xffffffffu, mx_a, 2));
        mx_b = fmaxf(mx_b, __shfl_xor_sync(0xffffffffu, mx_b, 1));
        mx_b = fmaxf(mx_b, __shfl_xor_sync(0xffffffffu, mx_b, 2));

        float nm_a = fmaxf(m_a, mx_a);
        float nm_b = fmaxf(m_b, mx_b);
        float corr_a = __expf(m_a - nm_a);
        float corr_b = __expf(m_b - nm_b);
        m_a = nm_a; m_b = nm_b;

        float sum_a = 0.f, sum_b = 0.f;
#pragma unroll
        for (int j = 0; j < 8; ++j) {
            s[j][0] = __expf(s[j][0] - nm_a);
            s[j][1] = __expf(s[j][1] - nm_a);
            s[j][2] = __expf(s[j][2] - nm_b);
            s[j][3] = __expf(s[j][3] - nm_b);
            sum_a += s[j][0] + s[j][1];
            sum_b += s[j][2] + s[j][3];
        }
        sum_a += __shfl_xor_sync(0xffffffffu, sum_a, 1);
        sum_a += __shfl_xor_sync(0xffffffffu, sum_a, 2);
        sum_b += __shfl_xor_sync(0xffffffffu, sum_b, 1);
        sum_b += __shfl_xor_sync(0xffffffffu, sum_b, 2);
        l_a = l_a * corr_a + sum_a;
        l_b = l_b * corr_b + sum_b;

#pragma unroll
        for (int nt = 0; nt < 16; ++nt) {
            o[nt][0] *= corr_a; o[nt][1] *= corr_a;
            o[nt][2] *= corr_b; o[nt][3] *= corr_b;
        }

        uint32_t ph[4][4], pl[4][4];
#pragma unroll
        for (int ks = 0; ks < 4; ++ks) {
            const float* t0 = s[2 * ks];
            const float* t1 = s[2 * ks + 1];
            float v0[8] = {t0[0], t0[1], t0[2], t0[3], t1[0], t1[1], t1[2], t1[3]};
            uint16_t hb[8]; float rs[8];
#pragma unroll
            for (int e = 0; e < 8; ++e) {
                bf16 hh = __float2bfloat16(v0[e]);
                hb[e] = bfbits(hh);
                rs[e] = v0[e] - __bfloat162float(hh);
            }
            ph[ks][0] = ((uint32_t)hb[1] << 16) | hb[0];
            ph[ks][1] = ((uint32_t)hb[3] << 16) | hb[2];
            ph[ks][2] = ((uint32_t)hb[5] << 16) | hb[4];
            ph[ks][3] = ((uint32_t)hb[7] << 16) | hb[6];
            uint16_t lb[8];
#pragma unroll
            for (int e = 0; e < 8; ++e) lb[e] = bfbits(__float2bfloat16(rs[e]));
            pl[ks][0] = ((uint32_t)lb[1] << 16) | lb[0];
            pl[ks][1] = ((uint32_t)lb[3] << 16) | lb[2];
            pl[ks][2] = ((uint32_t)lb[5] << 16) | lb[4];
            pl[ks][3] = ((uint32_t)lb[7] << 16) | lb[6];
        }

        // V must be resident now
        cp_wait<0>();
        __syncthreads();

#pragma unroll
        for (int nt = 0; nt < 16; ++nt) {
#pragma unroll
            for (int ks = 0; ks < 4; ++ks) {
                uint32_t bh[2], bl[2];
                int r = ks * 16 + (lane & 15);
                ldmx2t(bh, smb + AT_V_H + ASW(r, nt));
                ldmx2t(bl, smb + AT_V_L + ASW(r, nt));
                mma_bf16(o[nt], ph[ks], bh);
                mma_bf16(o[nt], ph[ks], bl);
                mma_bf16(o[nt], pl[ks], bh);
            }
        }
        __syncthreads();
    }

    const float inv_a = 1.f / l_a;
    const float inv_b = 1.f / l_b;
    const size_t ra = ((size_t)(b * SS + mb * 64 + rowA)) * HIDN + h * HD;
    const size_t rb = ra + (size_t)8 * HIDN;
#pragma unroll
    for (int nt = 0; nt < 16; ++nt) {
        int col = nt * 8 + (lane & 3) * 2;
        split_store(Ch, Cl, ra + col, o[nt][0] * inv_a, o[nt][1] * inv_a);
        split_store(Ch, Cl, rb + col, o[nt][2] * inv_b, o[nt][3] * inv_b);
    }
}

// ============================================================================
// Launch
// ============================================================================
extern "C" void kernel_launch(void* const* d_in, const int* in_sizes, int n_in,
                              void* d_out, int out_size)
{
    (void)in_sizes; (void)n_in; (void)out_size;
    const float* hs = (const float*)d_in[0];
    const float* Wq = (const float*)d_in[1];
    const float* Wk = (const float*)d_in[2];
    const float* Wv = (const float*)d_in[3];
    const float* Wo = (const float*)d_in[4];
    float* out = (float*)d_out;

    bf16 *hsh, *hsl, *wqkvh, *wqkvl, *woh, *wol;
    bf16 *qh, *ql, *kh, *kl, *vh, *vl, *ch, *cl;
    cudaGetSymbolAddress((void**)&hsh, g_hs_h);     cudaGetSymbolAddress((void**)&hsl, g_hs_l);
    cudaGetSymbolAddress((void**)&wqkvh, g_wqkv_h); cudaGetSymbolAddress((void**)&wqkvl, g_wqkv_l);
    cudaGetSymbolAddress((void**)&woh, g_wo_h);     cudaGetSymbolAddress((void**)&wol, g_wo_l);
    cudaGetSymbolAddress((void**)&qh, g_qh);        cudaGetSymbolAddress((void**)&ql, g_ql);
    cudaGetSymbolAddress((void**)&kh, g_kh);        cudaGetSymbolAddress((void**)&kl, g_kl);
    cudaGetSymbolAddress((void**)&vh, g_vh);        cudaGetSymbolAddress((void**)&vl, g_vl);
    cudaGetSymbolAddress((void**)&ch, g_ch);        cudaGetSymbolAddress((void**)&cl, g_cl);

    cudaFuncSetAttribute(gemm_hmma<0>, cudaFuncAttributeMaxDynamicSharedMemorySize, GSM_BYTES);
    cudaFuncSetAttribute(gemm_hmma<3>, cudaFuncAttributeMaxDynamicSharedMemorySize, GSM_BYTES);
    cudaFuncSetAttribute(attn_hmma, cudaFuncAttributeMaxDynamicSharedMemorySize, AT_SMEM);

    // 0: rope table
    rope_table<<<(SS * 64 + 255) / 256, 256>>>();
    // 1: all conversions in one kernel
    {
        size_t total = (size_t)MTOK * HIDN / 4 + 2 * (size_t)HIDN * HIDN / 4 + 2 * (size_t)KVW * HIDN / 4;
        cvt_all<<<(unsigned)((total + 255) / 256), 256>>>(hs, Wq, Wk, Wv, Wo);
    }
    // 2: merged Q|K|V projection (fused rope/scale/split epilogues)
    gemm_hmma<3><<<dim3(NQKV / 128, MTOK / 128), 256, GSM_BYTES>>>(hsh, hsl, wqkvh, wqkvl, nullptr, MTOK, NQKV, HIDN);
    // 3: attention (K/V split-group overlap)
    attn_hmma<<<dim3(SS / 64, NH, BB), 128, AT_SMEM>>>(qh, ql, kh, kl, vh, vl, ch, cl);
    // 4: output projection
    gemm_hmma<0><<<dim3(HIDN / 128, MTOK / 128), 256, GSM_BYTES>>>(ch, cl, woh, wol, out, MTOK, HIDN, HIDN);
}